// round 1
// baseline (speedup 1.0000x reference)
#include <cuda_runtime.h>

// ---------------- problem constants ----------------
#define NTOT 61440      // B*30 nodes
#define NB   2048       // batch (graphs)
#define NE   491520     // edges
#define NCH0 12
#define NCH1 128
#define NCH2 512
#define NCH3 128
#define FCK  3840       // 128*30
#define FCO  72

// ---------------- scratch (device globals; no allocs allowed) ----------------
__device__ float g_h[NTOT * 12];          // x @ W^T
__device__ float g_deg[NTOT];
__device__ float g_dinv[NTOT];
__device__ float g_acc[NTOT * 12];        // GCN scatter accumulator
__device__ float g_X0[12  * NTOT];        // [C][B*30]
__device__ float g_X1[128 * NTOT];
__device__ float g_X2[512L * NTOT];
__device__ float g_X3[128 * NTOT];
__device__ float g_fcwT[FCK * FCO];       // transposed fc weight [kk][j]
__device__ int   g_oddor;                 // 0 -> edge_index is int64

// ---------------- edge-index dtype detection ----------------
// If int64: odd 32-bit words are high halves == 0 (values < 2^31, nonneg).
// If int32: odd words are random edge values in [0,61440) -> OR != 0 w.h.p.
__global__ void k_detect(const int* __restrict__ w) {
    __shared__ int s;
    if (threadIdx.x == 0) s = 0;
    __syncthreads();
    int v = 0;
    for (int i = threadIdx.x; i < 8192; i += blockDim.x) v |= w[2 * i + 1];
    atomicOr(&s, v);
    __syncthreads();
    if (threadIdx.x == 0) g_oddor = s;
}

__device__ __forceinline__ void load_edge(const void* ei, int e, int is64,
                                          int& src, int& dst) {
    if (is64) {
        const long long* p = (const long long*)ei;
        src = (int)p[e];
        dst = (int)p[NE + e];
    } else {
        const int* p = (const int*)ei;
        src = p[e];
        dst = p[NE + e];
    }
}

// ---------------- GCN ----------------
// h = x @ W^T ; deg = 1 (self loop) ; acc = 0
__global__ void k_gcn_lin(const float* __restrict__ x, const float* __restrict__ w) {
    __shared__ float sw[144];
    int tid = threadIdx.x;
    if (tid < 144) sw[tid] = w[tid];
    __syncthreads();
    int n = blockIdx.x * blockDim.x + tid;
    if (n >= NTOT) return;
    float xv[12];
#pragma unroll
    for (int c = 0; c < 12; c++) xv[c] = x[n * 12 + c];
#pragma unroll
    for (int o = 0; o < 12; o++) {
        float s = 0.f;
#pragma unroll
        for (int c = 0; c < 12; c++) s = fmaf(sw[o * 12 + c], xv[c], s);
        g_h[n * 12 + o]   = s;
        g_acc[n * 12 + o] = 0.f;
    }
    g_deg[n] = 1.0f;
}

__global__ void k_deg(const void* ei) {
    int e = blockIdx.x * blockDim.x + threadIdx.x;
    if (e >= NE) return;
    int is64 = (g_oddor == 0);
    int src, dst;
    load_edge(ei, e, is64, src, dst);
    (void)src;
    atomicAdd(&g_deg[dst], 1.0f);
}

__global__ void k_dinv() {
    int n = blockIdx.x * blockDim.x + threadIdx.x;
    if (n >= NTOT) return;
    g_dinv[n] = rsqrtf(g_deg[n]);   // deg >= 1 always (self loop)
}

__global__ void k_scatter(const void* ei) {
    int e = blockIdx.x * blockDim.x + threadIdx.x;
    if (e >= NE) return;
    int is64 = (g_oddor == 0);
    int src, dst;
    load_edge(ei, e, is64, src, dst);
    float norm = g_dinv[src] * g_dinv[dst];
    const float* hs = &g_h[src * 12];
    float* ad = &g_acc[dst * 12];
#pragma unroll
    for (int c = 0; c < 12; c++) atomicAdd(&ad[c], norm * hs[c]);
}

// out[n] += dinv^2 * h[n] (self loop) + bias ; transpose to [C][B*30]
__global__ void k_gcn_out(const float* __restrict__ b) {
    int n = blockIdx.x * blockDim.x + threadIdx.x;
    if (n >= NTOT) return;
    float di = g_dinv[n];
    float sl = di * di;
#pragma unroll
    for (int c = 0; c < 12; c++) {
        g_X0[c * NTOT + n] = g_acc[n * 12 + c] + sl * g_h[n * 12 + c] + b[c];
    }
}

// ---------------- TCN block: causal dilated conv(k=3) + 1x1 downsample ----------------
// Xout[o, g*30+t] = relu( relu(sum_{c,k} cw[o,c,k]*Xin[c, g*30+t-(2-k)*DIL] + cb[o])
//                         + sum_c dw[o,c]*Xin[c, g*30+t] + db[o] )
// smem halo coords: sx[cc][j][u] = Xin[c, g*30 + u - 2*DIL] (zero for u<2*DIL),
// so tap k reads u = t + k*DIL; downsample reads u = t + 2*DIL.
template <int CIN, int COUT, int DIL, int BK>
__global__ __launch_bounds__(240, 2) void k_tcn(
    const float* __restrict__ Xin, const float* __restrict__ cw,
    const float* __restrict__ cb, const float* __restrict__ dw,
    const float* __restrict__ db, float* __restrict__ Xout) {
    constexpr int BM  = 64;
    constexpr int GPB = 4;
    constexpr int SXW = 30 + 2 * DIL;

    __shared__ float sx[BK][GPB][SXW];
    __shared__ float sw[BK][3][BM];
    __shared__ float sdw[BK][BM];

    const int tx  = threadIdx.x;            // 0..29 (time)
    const int ty  = threadIdx.y;            // 0..7  (row group)
    const int tid = ty * 30 + tx;
    const int m0  = blockIdx.x * BM;        // output-channel base
    const int g0  = blockIdx.y * GPB;       // graph base

    float acc1[GPB][8];
    float acc2[GPB][8];
#pragma unroll
    for (int j = 0; j < GPB; j++)
#pragma unroll
        for (int m = 0; m < 8; m++) { acc1[j][m] = 0.f; acc2[j][m] = 0.f; }

    for (int c0 = 0; c0 < CIN; c0 += BK) {
        // ---- load activation tile with causal halo ----
        for (int idx = tid; idx < BK * GPB * SXW; idx += 240) {
            int cc = idx / (GPB * SXW);
            int r  = idx % (GPB * SXW);
            int j  = r / SXW;
            int u  = r % SXW;
            int t  = u - 2 * DIL;
            float v = 0.f;
            if (t >= 0) v = Xin[(size_t)(c0 + cc) * NTOT + (g0 + j) * 30 + t];
            sx[cc][j][u] = v;
        }
        // ---- load weight tile (cc fastest for coalescing) ----
        for (int idx = tid; idx < BK * BM; idx += 240) {
            int cc  = idx % BK;
            int row = idx / BK;
            int gr  = m0 + row;
            const float* wp = &cw[((size_t)gr * CIN + (c0 + cc)) * 3];
            sw[cc][0][row] = wp[0];
            sw[cc][1][row] = wp[1];
            sw[cc][2][row] = wp[2];
            sdw[cc][row]   = dw[(size_t)gr * CIN + (c0 + cc)];
        }
        __syncthreads();

#pragma unroll 4
        for (int cc = 0; cc < BK; cc++) {
            float w0[8], w1[8], w2[8], wd[8];
#pragma unroll
            for (int m = 0; m < 8; m++) {
                int row = ty * 8 + m;
                w0[m] = sw[cc][0][row];
                w1[m] = sw[cc][1][row];
                w2[m] = sw[cc][2][row];
                wd[m] = sdw[cc][row];
            }
#pragma unroll
            for (int j = 0; j < GPB; j++) {
                float x0 = sx[cc][j][tx];
                float x1 = sx[cc][j][tx + DIL];
                float x2 = sx[cc][j][tx + 2 * DIL];
#pragma unroll
                for (int m = 0; m < 8; m++) {
                    float a = acc1[j][m];
                    a = fmaf(w0[m], x0, a);
                    a = fmaf(w1[m], x1, a);
                    a = fmaf(w2[m], x2, a);
                    acc1[j][m] = a;
                    acc2[j][m] = fmaf(wd[m], x2, acc2[j][m]);
                }
            }
        }
        __syncthreads();
    }

    // ---- epilogue: relu(conv+cb), add residual, relu ----
#pragma unroll
    for (int m = 0; m < 8; m++) {
        int row = ty * 8 + m;
        int gr  = m0 + row;
        float bc = cb[gr];
        float bd = db[gr];
#pragma unroll
        for (int j = 0; j < GPB; j++) {
            float o = fmaxf(acc1[j][m] + bc, 0.f);
            float y = fmaxf(o + acc2[j][m] + bd, 0.f);
            Xout[(size_t)gr * NTOT + (g0 + j) * 30 + tx] = y;
        }
    }
}

// ---------------- FC prep: transpose fc_w, init out with bias ----------------
__global__ void k_prep(const float* __restrict__ fcw, const float* __restrict__ fcb,
                       float* __restrict__ out) {
    int idx = blockIdx.x * blockDim.x + threadIdx.x;
    if (idx < FCO * FCK) {
        int j  = idx / FCK;
        int kk = idx % FCK;
        g_fcwT[kk * FCO + j] = fcw[idx];   // coalesced read
    }
    if (idx < NB * FCO) out[idx] = fcb[idx % FCO];
}

// ---------------- FC: out[g,j] += sum_kk fc_wT[kk][j] * X3flat[g][kk] ----------------
__global__ void k_fc(float* __restrict__ out) {
    extern __shared__ float sxf[];          // [GF][3840]
    const int GF = 8;
    int g0  = blockIdx.x * GF;
    int tid = threadIdx.x;                  // 288 threads
    for (int idx = tid; idx < GF * FCK; idx += 288) {
        int g  = idx / FCK;
        int kk = idx % FCK;
        int c  = kk / 30;
        int t  = kk % 30;
        sxf[idx] = g_X3[(size_t)c * NTOT + (g0 + g) * 30 + t];
    }
    __syncthreads();
    int j = tid % FCO;
    int q = tid / FCO;                      // 0..3 K-quarter
    float acc[GF];
#pragma unroll
    for (int g = 0; g < GF; g++) acc[g] = 0.f;
    int k0 = q * (FCK / 4);
    for (int kk = k0; kk < k0 + FCK / 4; kk++) {
        float w = g_fcwT[kk * FCO + j];
#pragma unroll
        for (int g = 0; g < GF; g++) acc[g] = fmaf(w, sxf[g * FCK + kk], acc[g]);
    }
#pragma unroll
    for (int g = 0; g < GF; g++) atomicAdd(&out[(g0 + g) * FCO + j], acc[g]);
}

// ---------------- launch ----------------
extern "C" void kernel_launch(void* const* d_in, const int* in_sizes, int n_in,
                              void* d_out, int out_size) {
    const float* x     = (const float*)d_in[0];
    const void*  ei    = d_in[1];
    const float* gcnw  = (const float*)d_in[2];
    const float* gcnb  = (const float*)d_in[3];
    const float* cw0   = (const float*)d_in[4];
    const float* cb0   = (const float*)d_in[5];
    const float* dw0   = (const float*)d_in[6];
    const float* db0   = (const float*)d_in[7];
    const float* cw1   = (const float*)d_in[8];
    const float* cb1   = (const float*)d_in[9];
    const float* dw1   = (const float*)d_in[10];
    const float* db1   = (const float*)d_in[11];
    const float* cw2   = (const float*)d_in[12];
    const float* cb2   = (const float*)d_in[13];
    const float* dw2   = (const float*)d_in[14];
    const float* db2   = (const float*)d_in[15];
    const float* fcw   = (const float*)d_in[16];
    const float* fcb   = (const float*)d_in[17];
    float* out = (float*)d_out;

    float *pX0, *pX1, *pX2, *pX3;
    cudaGetSymbolAddress((void**)&pX0, g_X0);
    cudaGetSymbolAddress((void**)&pX1, g_X1);
    cudaGetSymbolAddress((void**)&pX2, g_X2);
    cudaGetSymbolAddress((void**)&pX3, g_X3);

    // GCN
    k_detect<<<1, 256>>>((const int*)ei);
    k_gcn_lin<<<(NTOT + 255) / 256, 256>>>(x, gcnw);
    k_deg<<<(NE + 255) / 256, 256>>>(ei);
    k_dinv<<<(NTOT + 255) / 256, 256>>>();
    k_scatter<<<(NE + 255) / 256, 256>>>(ei);
    k_gcn_out<<<(NTOT + 255) / 256, 256>>>(gcnb);

    // FC prep (independent; overlaps nothing but cheap)
    k_prep<<<(FCO * FCK + 255) / 256, 256>>>(fcw, fcb, out);

    // TCN blocks
    dim3 tb(30, 8);
    k_tcn<12, 128, 1, 12><<<dim3(128 / 64, NB / 4), tb>>>(pX0, cw0, cb0, dw0, db0, pX1);
    k_tcn<128, 512, 3, 16><<<dim3(512 / 64, NB / 4), tb>>>(pX1, cw1, cb1, dw1, db1, pX2);
    k_tcn<512, 128, 9, 16><<<dim3(128 / 64, NB / 4), tb>>>(pX2, cw2, cb2, dw2, db2, pX3);

    // FC
    cudaFuncSetAttribute(k_fc, cudaFuncAttributeMaxDynamicSharedMemorySize,
                         8 * FCK * (int)sizeof(float));
    k_fc<<<NB / 8, 288, 8 * FCK * (int)sizeof(float)>>>(out);
}

// round 3
// speedup vs baseline: 1.8582x; 1.8582x over previous
#include <cuda_runtime.h>
#include <cstdint>

// ---------------- problem constants ----------------
#define NTOT 61440      // B*30 positions/nodes
#define NB   2048
#define NE   491520
#define FCK  3840       // 128*30
#define FCO  72

// ---------------- scratch ----------------
__device__ float g_h[NTOT * 12];
__device__ float g_deg[NTOT];
__device__ float g_dinv[NTOT];
__device__ float g_acc[NTOT * 12];
__device__ float g_X0[NTOT * 12];          // [pos][12]
__device__ float g_X1[(size_t)NTOT * 128]; // [pos][128]
__device__ float g_X2[(size_t)NTOT * 512]; // [pos][512]
__device__ float g_X3[(size_t)NTOT * 128]; // [pos][128]
__device__ float g_fcwT[FCK * FCO];
__device__ int   g_oddor;

// ---------------- helpers ----------------
__device__ __forceinline__ uint32_t f2tf32(float f) {
    uint32_t u;
    asm("cvt.rna.tf32.f32 %0, %1;" : "=r"(u) : "f"(f));
    return u;
}
__device__ __forceinline__ void mma8(float* d, const uint32_t* a, const uint32_t* b) {
    asm volatile(
        "mma.sync.aligned.m16n8k8.row.col.f32.tf32.tf32.f32 "
        "{%0,%1,%2,%3}, {%4,%5,%6,%7}, {%8,%9}, {%0,%1,%2,%3};"
        : "+f"(d[0]), "+f"(d[1]), "+f"(d[2]), "+f"(d[3])
        : "r"(a[0]), "r"(a[1]), "r"(a[2]), "r"(a[3]), "r"(b[0]), "r"(b[1]));
}

// ---------------- edge dtype detect ----------------
__global__ void k_detect(const int* __restrict__ w) {
    __shared__ int s;
    if (threadIdx.x == 0) s = 0;
    __syncthreads();
    int v = 0;
    for (int i = threadIdx.x; i < 8192; i += blockDim.x) v |= w[2 * i + 1];
    atomicOr(&s, v);
    __syncthreads();
    if (threadIdx.x == 0) g_oddor = s;
}
__device__ __forceinline__ void load_edge(const void* ei, int e, int is64, int& src, int& dst) {
    if (is64) {
        const long long* p = (const long long*)ei;
        src = (int)p[e]; dst = (int)p[NE + e];
    } else {
        const int* p = (const int*)ei;
        src = p[e]; dst = p[NE + e];
    }
}

// ---------------- GCN ----------------
__global__ void k_gcn_lin(const float* __restrict__ x, const float* __restrict__ w) {
    __shared__ float sw[144];
    int tid = threadIdx.x;
    if (tid < 144) sw[tid] = w[tid];
    __syncthreads();
    int n = blockIdx.x * blockDim.x + tid;
    if (n >= NTOT) return;
    float xv[12];
#pragma unroll
    for (int c = 0; c < 12; c++) xv[c] = x[n * 12 + c];
#pragma unroll
    for (int o = 0; o < 12; o++) {
        float s = 0.f;
#pragma unroll
        for (int c = 0; c < 12; c++) s = fmaf(sw[o * 12 + c], xv[c], s);
        g_h[n * 12 + o] = s;
        g_acc[n * 12 + o] = 0.f;
    }
    g_deg[n] = 1.0f;
}
__global__ void k_deg(const void* ei) {
    int e = blockIdx.x * blockDim.x + threadIdx.x;
    if (e >= NE) return;
    int src, dst;
    load_edge(ei, e, g_oddor == 0, src, dst);
    (void)src;
    atomicAdd(&g_deg[dst], 1.0f);
}
__global__ void k_dinv() {
    int n = blockIdx.x * blockDim.x + threadIdx.x;
    if (n < NTOT) g_dinv[n] = rsqrtf(g_deg[n]);
}
__global__ void k_scatter(const void* ei) {
    int e = blockIdx.x * blockDim.x + threadIdx.x;
    if (e >= NE) return;
    int src, dst;
    load_edge(ei, e, g_oddor == 0, src, dst);
    float norm = g_dinv[src] * g_dinv[dst];
    const float* hs = &g_h[src * 12];
    float* ad = &g_acc[dst * 12];
#pragma unroll
    for (int c = 0; c < 12; c++) atomicAdd(&ad[c], norm * hs[c]);
}
__global__ void k_gcn_out(const float* __restrict__ b) {
    int n = blockIdx.x * blockDim.x + threadIdx.x;
    if (n >= NTOT) return;
    float di = g_dinv[n];
    float sl = di * di;
#pragma unroll
    for (int c = 0; c < 12; c++)
        g_X0[n * 12 + c] = g_acc[n * 12 + c] + sl * g_h[n * 12 + c] + b[c];
}

// ---------------- block 0 (12 -> 128, dil=1), scalar ----------------
__global__ __launch_bounds__(128) void k_tcn0(
    const float* __restrict__ cw, const float* __restrict__ cb,
    const float* __restrict__ dw, const float* __restrict__ db) {
    __shared__ float sx[34][12];
    int tid = threadIdx.x;
    int p0 = blockIdx.x * 32;
    for (int i = tid; i < 34 * 12; i += 128) {
        int r = i / 12, c = i % 12;
        int p = p0 - 2 + r;
        sx[r][c] = (p >= 0 && p < NTOT) ? g_X0[p * 12 + c] : 0.f;
    }
    __syncthreads();
    int ch = tid;
    float w[36], wd[12];
#pragma unroll
    for (int i = 0; i < 36; i++) w[i] = cw[ch * 36 + i];
#pragma unroll
    for (int i = 0; i < 12; i++) wd[i] = dw[ch * 12 + i];
    float bc = cb[ch], bd = db[ch];
    for (int j = 0; j < 32; j++) {
        int p = p0 + j;
        int t = p % 30;
        float acc = 0.f, accd = 0.f;
#pragma unroll
        for (int k = 0; k < 3; k++) {
            if (t - 2 + k >= 0) {
#pragma unroll
                for (int ci = 0; ci < 12; ci++)
                    acc = fmaf(w[ci * 3 + k], sx[j + k][ci], acc);
            }
        }
#pragma unroll
        for (int ci = 0; ci < 12; ci++) accd = fmaf(wd[ci], sx[j + 2][ci], accd);
        g_X1[(size_t)p * 128 + ch] = fmaxf(fmaxf(acc + bc, 0.f) + accd + bd, 0.f);
    }
}

// ---------------- tf32 mma.sync TCN block ----------------
// CTA: 64 out-ch x 128 pos; 8 warps -> 32x32 each (2 m16 x 4 n8 tiles).
// K streamed in 32-channel chunks; smem: B[tap][pos][cc] (stride 36),
// A[o][cc*3+tap] (stride 100), Ad[o][cc] (stride 36). Down reuses tap-2 B.
#define SB_STRIDE 36
#define SA_STRIDE 100
#define SB_TAP 4608          // 128*36 floats
#define OFF_A 13824          // 3*4608
#define OFF_AD 20224         // OFF_A + 64*100
#define SMEM_TCN_FLOATS 22528
#define SMEM_TCN_BYTES (SMEM_TCN_FLOATS * 4)

template <int CIN, int COUT, int DIL>
__global__ __launch_bounds__(256, 2) void k_tcnM(
    const float* __restrict__ Xin, const float* __restrict__ cw,
    const float* __restrict__ cb, const float* __restrict__ dw,
    const float* __restrict__ db, float* __restrict__ Xout) {
    extern __shared__ uint32_t sm[];
    uint32_t* sB = sm;
    uint32_t* sA = sm + OFF_A;
    uint32_t* sAd = sm + OFF_AD;

    const int tid = threadIdx.x;
    const int w = tid >> 5, lane = tid & 31;
    const int lr = lane >> 2, lc = lane & 3;
    const int mh = w & 1;        // M half (32 ch)
    const int nq = w >> 1;       // N quad (32 pos)
    const int m0 = blockIdx.x * 64;
    const int n0 = blockIdx.y * 128;

    float acc1[2][4][4], acc2[2][4][4];
#pragma unroll
    for (int mt = 0; mt < 2; mt++)
#pragma unroll
        for (int nt = 0; nt < 4; nt++)
#pragma unroll
            for (int r = 0; r < 4; r++) { acc1[mt][nt][r] = 0.f; acc2[mt][nt][r] = 0.f; }

    for (int c0 = 0; c0 < CIN; c0 += 32) {
        __syncthreads();
        // ---- stage B: activations, 3 causal shifts ----
        for (int idx = tid; idx < 3 * 128 * 32; idx += 256) {
            int cc = idx & 31;
            int pos = (idx >> 5) & 127;
            int tap = idx >> 12;
            int p = n0 + pos;
            int g = p / 30, t = p - g * 30;
            int st = t - (2 - tap) * DIL;
            uint32_t v = 0;
            if (st >= 0) v = f2tf32(Xin[(size_t)(g * 30 + st) * CIN + c0 + cc]);
            sB[tap * SB_TAP + pos * SB_STRIDE + cc] = v;
        }
        // ---- stage A: conv weights [o][cc*3+tap] ----
        for (int idx = tid; idx < 64 * 96; idx += 256) {
            int ck = idx % 96;
            int o = idx / 96;
            sA[o * SA_STRIDE + ck] = f2tf32(cw[((size_t)(m0 + o) * CIN + c0) * 3 + ck]);
        }
        // ---- stage Ad: downsample weights ----
        for (int idx = tid; idx < 64 * 32; idx += 256) {
            int cc = idx & 31;
            int o = idx >> 5;
            sAd[o * SB_STRIDE + cc] = f2tf32(dw[(size_t)(m0 + o) * CIN + c0 + cc]);
        }
        __syncthreads();

#pragma unroll
        for (int ks = 0; ks < 4; ks++) {
            const int cb8 = ks * 8;
            uint32_t b[4][2];
#pragma unroll
            for (int tap = 0; tap < 3; tap++) {
#pragma unroll
                for (int nt = 0; nt < 4; nt++) {
                    int pl = nq * 32 + nt * 8 + lr;
                    b[nt][0] = sB[tap * SB_TAP + pl * SB_STRIDE + cb8 + lc];
                    b[nt][1] = sB[tap * SB_TAP + pl * SB_STRIDE + cb8 + lc + 4];
                }
                uint32_t a[2][4];
#pragma unroll
                for (int mt = 0; mt < 2; mt++) {
                    int orow = mh * 32 + mt * 16 + lr;
                    int ck0 = (cb8 + lc) * 3 + tap;
                    int ck1 = (cb8 + lc + 4) * 3 + tap;
                    a[mt][0] = sA[orow * SA_STRIDE + ck0];
                    a[mt][1] = sA[(orow + 8) * SA_STRIDE + ck0];
                    a[mt][2] = sA[orow * SA_STRIDE + ck1];
                    a[mt][3] = sA[(orow + 8) * SA_STRIDE + ck1];
                }
#pragma unroll
                for (int mt = 0; mt < 2; mt++)
#pragma unroll
                    for (int nt = 0; nt < 4; nt++)
                        mma8(acc1[mt][nt], a[mt], b[nt]);
            }
            // ---- downsample: reuse tap-2 B frags ----
            uint32_t ad[2][4];
#pragma unroll
            for (int mt = 0; mt < 2; mt++) {
                int orow = mh * 32 + mt * 16 + lr;
                ad[mt][0] = sAd[orow * SB_STRIDE + cb8 + lc];
                ad[mt][1] = sAd[(orow + 8) * SB_STRIDE + cb8 + lc];
                ad[mt][2] = sAd[orow * SB_STRIDE + cb8 + lc + 4];
                ad[mt][3] = sAd[(orow + 8) * SB_STRIDE + cb8 + lc + 4];
            }
#pragma unroll
            for (int mt = 0; mt < 2; mt++)
#pragma unroll
                for (int nt = 0; nt < 4; nt++)
                    mma8(acc2[mt][nt], ad[mt], b[nt]);
        }
    }

    // ---- epilogue: relu(relu(conv+cb)+down+db), smem transpose, float4 STG ----
    __syncthreads();
    float* sO = (float*)sm;  // [128 pos][64 ch] stride 68
#pragma unroll
    for (int mt = 0; mt < 2; mt++) {
        int ob = m0 + mh * 32 + mt * 16 + lr;
        float bc0 = cb[ob], bc1 = cb[ob + 8];
        float bd0 = db[ob], bd1 = db[ob + 8];
#pragma unroll
        for (int nt = 0; nt < 4; nt++) {
#pragma unroll
            for (int r = 0; r < 4; r++) {
                float bc = (r >= 2) ? bc1 : bc0;
                float bd = (r >= 2) ? bd1 : bd0;
                int oo = mh * 32 + mt * 16 + lr + ((r >= 2) ? 8 : 0);
                int po = nq * 32 + nt * 8 + lc * 2 + (r & 1);
                float y = fmaxf(fmaxf(acc1[mt][nt][r] + bc, 0.f) + acc2[mt][nt][r] + bd, 0.f);
                sO[po * 68 + oo] = y;
            }
        }
    }
    __syncthreads();
    for (int idx = tid; idx < 128 * 16; idx += 256) {
        int r = idx >> 4, q = idx & 15;
        float4 v = *(float4*)&sO[r * 68 + q * 4];
        *(float4*)(Xout + (size_t)(n0 + r) * COUT + m0 + q * 4) = v;
    }
}

// ---------------- FC ----------------
__global__ void k_prep(const float* __restrict__ fcw, const float* __restrict__ fcb,
                       float* __restrict__ out) {
    int idx = blockIdx.x * blockDim.x + threadIdx.x;
    if (idx < FCO * FCK) {
        int j = idx / FCK, kk = idx % FCK;
        g_fcwT[kk * FCO + j] = fcw[idx];
    }
    if (idx < NB * FCO) out[idx] = fcb[idx % FCO];
}
__global__ void k_fc(float* __restrict__ out) {
    extern __shared__ float sxf[];  // [8][3840]
    const int GF = 8;
    int g0 = blockIdx.x * GF;
    int tid = threadIdx.x;  // 288
    for (int idx = tid; idx < GF * FCK; idx += 288) {
        int g = idx / FCK;
        int rem = idx - g * FCK;
        int pos = rem >> 7, c = rem & 127;  // c fastest -> coalesced LDG
        sxf[g * FCK + c * 30 + pos] = g_X3[((size_t)(g0 + g) * 30 + pos) * 128 + c];
    }
    __syncthreads();
    int j = tid % FCO, q = tid / FCO;
    float acc[GF];
#pragma unroll
    for (int g = 0; g < GF; g++) acc[g] = 0.f;
    int k0 = q * (FCK / 4);
    for (int kk = k0; kk < k0 + FCK / 4; kk++) {
        float wv = g_fcwT[kk * FCO + j];
#pragma unroll
        for (int g = 0; g < GF; g++) acc[g] = fmaf(wv, sxf[g * FCK + kk], acc[g]);
    }
#pragma unroll
    for (int g = 0; g < GF; g++) atomicAdd(&out[(g0 + g) * FCO + j], acc[g]);
}

// ---------------- launch ----------------
extern "C" void kernel_launch(void* const* d_in, const int* in_sizes, int n_in,
                              void* d_out, int out_size) {
    const float* x    = (const float*)d_in[0];
    const void*  ei   = d_in[1];
    const float* gcnw = (const float*)d_in[2];
    const float* gcnb = (const float*)d_in[3];
    const float* cw0  = (const float*)d_in[4];
    const float* cb0  = (const float*)d_in[5];
    const float* dw0  = (const float*)d_in[6];
    const float* db0  = (const float*)d_in[7];
    const float* cw1  = (const float*)d_in[8];
    const float* cb1  = (const float*)d_in[9];
    const float* dw1  = (const float*)d_in[10];
    const float* db1  = (const float*)d_in[11];
    const float* cw2  = (const float*)d_in[12];
    const float* cb2  = (const float*)d_in[13];
    const float* dw2  = (const float*)d_in[14];
    const float* db2  = (const float*)d_in[15];
    const float* fcw  = (const float*)d_in[16];
    const float* fcb  = (const float*)d_in[17];
    float* out = (float*)d_out;

    float *pX1, *pX2, *pX3;
    cudaGetSymbolAddress((void**)&pX1, g_X1);
    cudaGetSymbolAddress((void**)&pX2, g_X2);
    cudaGetSymbolAddress((void**)&pX3, g_X3);

    k_detect<<<1, 256>>>((const int*)ei);
    k_gcn_lin<<<(NTOT + 255) / 256, 256>>>(x, gcnw);
    k_deg<<<(NE + 255) / 256, 256>>>(ei);
    k_dinv<<<(NTOT + 255) / 256, 256>>>();
    k_scatter<<<(NE + 255) / 256, 256>>>(ei);
    k_gcn_out<<<(NTOT + 255) / 256, 256>>>(gcnb);

    k_prep<<<(FCO * FCK + 255) / 256, 256>>>(fcw, fcb, out);

    k_tcn0<<<NTOT / 32, 128>>>(cw0, cb0, dw0, db0);

    cudaFuncSetAttribute(k_tcnM<128, 512, 3>,
                         cudaFuncAttributeMaxDynamicSharedMemorySize, SMEM_TCN_BYTES);
    cudaFuncSetAttribute(k_tcnM<512, 128, 9>,
                         cudaFuncAttributeMaxDynamicSharedMemorySize, SMEM_TCN_BYTES);
    k_tcnM<128, 512, 3><<<dim3(8, NTOT / 128), 256, SMEM_TCN_BYTES>>>(pX1, cw1, cb1, dw1, db1, pX2);
    k_tcnM<512, 128, 9><<<dim3(2, NTOT / 128), 256, SMEM_TCN_BYTES>>>(pX2, cw2, cb2, dw2, db2, pX3);

    cudaFuncSetAttribute(k_fc, cudaFuncAttributeMaxDynamicSharedMemorySize,
                         8 * FCK * (int)sizeof(float));
    k_fc<<<NB / 8, 288, 8 * FCK * (int)sizeof(float)>>>(out);
}

// round 4
// speedup vs baseline: 2.7543x; 1.4822x over previous
#include <cuda_runtime.h>
#include <cstdint>

// ---------------- problem constants ----------------
#define NTOT 61440      // B*30 positions/nodes
#define NB   2048
#define NE   491520
#define FCK  3840       // 128*30
#define FCO  72

// ---------------- scratch ----------------
__device__ float g_h[NTOT * 12];
__device__ float g_deg[NTOT];              // edge-degree (self loop added as +1)
__device__ float g_acc[NTOT * 12];
__device__ float g_X1[(size_t)NTOT * 128]; // [pos][128]
__device__ float g_X2[(size_t)NTOT * 512]; // [pos][512]
__device__ float g_X3[(size_t)NTOT * 128]; // [pos][128]
__device__ float g_fcwT[FCK * FCO];

// ---------------- helpers ----------------
__device__ __forceinline__ uint32_t f2tf32(float f) {
    uint32_t u;
    asm("cvt.rna.tf32.f32 %0, %1;" : "=r"(u) : "f"(f));
    return u;
}
__device__ __forceinline__ void mma8(float* d, const uint32_t* a, const uint32_t* b) {
    asm volatile(
        "mma.sync.aligned.m16n8k8.row.col.f32.tf32.tf32.f32 "
        "{%0,%1,%2,%3}, {%4,%5,%6,%7}, {%8,%9}, {%0,%1,%2,%3};"
        : "+f"(d[0]), "+f"(d[1]), "+f"(d[2]), "+f"(d[3])
        : "r"(a[0]), "r"(a[1]), "r"(a[2]), "r"(a[3]), "r"(b[0]), "r"(b[1]));
}

// per-block edge-dtype detection: OR first 64 odd 32-bit words.
// int64 indices -> high halves are all 0; int32 -> random values, nonzero w.h.p.
__device__ __forceinline__ int detect_is64(const void* ei, int tid) {
    __shared__ int sdet;
    if (tid == 0) sdet = 0;
    __syncthreads();
    if (tid < 64) {
        int v = ((const int*)ei)[2 * tid + 1];
        if (v) atomicOr(&sdet, 1);
    }
    __syncthreads();
    return sdet == 0;
}
__device__ __forceinline__ void load_edge(const void* ei, int e, int is64, int& src, int& dst) {
    if (is64) {
        const long long* p = (const long long*)ei;
        src = (int)p[e]; dst = (int)p[NE + e];
    } else {
        const int* p = (const int*)ei;
        src = p[e]; dst = p[NE + e];
    }
}

// ---------------- GCN: fused lin + degree ----------------
// blocks [0,240): h = x W^T ; blocks [240, 2160): deg atomic counts
__global__ __launch_bounds__(256) void k_linDeg(
    const float* __restrict__ x, const float* __restrict__ w, const void* ei) {
    int tid = threadIdx.x;
    if (blockIdx.x < 240) {
        __shared__ float sw[144];
        if (tid < 144) sw[tid] = w[tid];
        __syncthreads();
        int n = blockIdx.x * 256 + tid;
        float xv[12];
#pragma unroll
        for (int c = 0; c < 12; c++) xv[c] = x[n * 12 + c];
#pragma unroll
        for (int o = 0; o < 12; o++) {
            float s = 0.f;
#pragma unroll
            for (int c = 0; c < 12; c++) s = fmaf(sw[o * 12 + c], xv[c], s);
            g_h[n * 12 + o] = s;
        }
    } else {
        int is64 = detect_is64(ei, tid);
        int e = (blockIdx.x - 240) * 256 + tid;
        int src, dst;
        load_edge(ei, e, is64, src, dst);
        (void)src;
        atomicAdd(&g_deg[dst], 1.0f);
    }
}

__global__ __launch_bounds__(256) void k_scatter(const void* ei) {
    int tid = threadIdx.x;
    int is64 = detect_is64(ei, tid);
    int e = blockIdx.x * 256 + tid;
    int src, dst;
    load_edge(ei, e, is64, src, dst);
    float norm = rsqrtf(g_deg[src] + 1.0f) * rsqrtf(g_deg[dst] + 1.0f);
    float4 h0 = *(const float4*)(g_h + src * 12);
    float4 h1 = *(const float4*)(g_h + src * 12 + 4);
    float4 h2 = *(const float4*)(g_h + src * 12 + 8);
    float* ad = &g_acc[dst * 12];
    atomicAdd(ad + 0, norm * h0.x);  atomicAdd(ad + 1, norm * h0.y);
    atomicAdd(ad + 2, norm * h0.z);  atomicAdd(ad + 3, norm * h0.w);
    atomicAdd(ad + 4, norm * h1.x);  atomicAdd(ad + 5, norm * h1.y);
    atomicAdd(ad + 6, norm * h1.z);  atomicAdd(ad + 7, norm * h1.w);
    atomicAdd(ad + 8, norm * h2.x);  atomicAdd(ad + 9, norm * h2.y);
    atomicAdd(ad + 10, norm * h2.z); atomicAdd(ad + 11, norm * h2.w);
}

// ---------------- fused gcn_out + TCN block 0 (12 -> 128, dil=1) ----------------
__global__ __launch_bounds__(128) void k_tcn0f(
    const float* __restrict__ cw, const float* __restrict__ cb,
    const float* __restrict__ dw, const float* __restrict__ db,
    const float* __restrict__ gcnb) {
    __shared__ float sx[34][12];
    int tid = threadIdx.x;
    int p0 = blockIdx.x * 32;
    for (int i = tid; i < 34 * 12; i += 128) {
        int r = i / 12, c = i % 12;
        int p = p0 - 2 + r;
        float v = 0.f;
        if (p >= 0) {
            float di = rsqrtf(g_deg[p] + 1.0f);
            v = g_acc[p * 12 + c] + di * di * g_h[p * 12 + c] + gcnb[c];
        }
        sx[r][c] = v;
    }
    __syncthreads();
    int ch = tid;
    float w[36], wd[12];
#pragma unroll
    for (int i = 0; i < 36; i++) w[i] = cw[ch * 36 + i];
#pragma unroll
    for (int i = 0; i < 12; i++) wd[i] = dw[ch * 12 + i];
    float bc = cb[ch], bd = db[ch];
    for (int j = 0; j < 32; j++) {
        int p = p0 + j;
        int t = p % 30;
        float acc = 0.f, accd = 0.f;
#pragma unroll
        for (int k = 0; k < 3; k++) {
            if (t - 2 + k >= 0) {
#pragma unroll
                for (int ci = 0; ci < 12; ci++)
                    acc = fmaf(w[ci * 3 + k], sx[j + k][ci], acc);
            }
        }
#pragma unroll
        for (int ci = 0; ci < 12; ci++) accd = fmaf(wd[ci], sx[j + 2][ci], accd);
        g_X1[(size_t)p * 128 + ch] = fmaxf(fmaxf(acc + bc, 0.f) + accd + bd, 0.f);
    }
}

// ---------------- tf32 mma.sync TCN block, graph-aligned tiles ----------------
// CTA: 64 out-ch x 4 graphs (each padded to 32 cols => N=128).
// Single halo B buffer [gi][u=t+tap*DIL in 0..W][cc] stride 36, W=32+2*DIL;
// tap-k fragment = uniform +tap*DIL*36 offset. 8 warps: 2 M-halves x 4 graphs.
template <int CIN, int COUT, int DIL>
__global__ __launch_bounds__(256, 2) void k_tcnM(
    const float* __restrict__ Xin, const float* __restrict__ cw,
    const float* __restrict__ cb, const float* __restrict__ dw,
    const float* __restrict__ db, float* __restrict__ Xout) {
    constexpr int W = 32 + 2 * DIL;
    constexpr int W36 = W * 36;
    extern __shared__ uint32_t sm[];
    uint32_t* sB = sm;                  // 4*W36
    uint32_t* sA = sm + 4 * W36;        // 64*100
    uint32_t* sAd = sA + 64 * 100;      // 64*36

    const int tid = threadIdx.x;
    const int w = tid >> 5, lane = tid & 31;
    const int lr = lane >> 2, lc = lane & 3;
    const int mh = w & 1;               // M half (32 ch)
    const int nq = w >> 1;              // graph within CTA
    const int m0 = blockIdx.x * 64;
    const int g0 = blockIdx.y * 4;

    float acc1[2][4][4], acc2[2][4][4];
#pragma unroll
    for (int mt = 0; mt < 2; mt++)
#pragma unroll
        for (int nt = 0; nt < 4; nt++)
#pragma unroll
            for (int r = 0; r < 4; r++) { acc1[mt][nt][r] = 0.f; acc2[mt][nt][r] = 0.f; }

    const int laneB = nq * W36 + lr * 36 + lc;

    for (int c0 = 0; c0 < CIN; c0 += 32) {
        __syncthreads();
        // ---- stage B: halo window per graph, float4 along channels ----
        for (int idx = tid; idx < 4 * W * 8; idx += 256) {
            int gi = idx / (W * 8);
            int r = idx - gi * W * 8;
            int u = r >> 3, q = r & 7;
            int t = u - 2 * DIL;
            float4 v = make_float4(0.f, 0.f, 0.f, 0.f);
            if (t >= 0 && t < 30)
                v = *(const float4*)(Xin + (size_t)((g0 + gi) * 30 + t) * CIN + c0 + q * 4);
            uint32_t* p = sB + gi * W36 + u * 36 + q * 4;
            p[0] = f2tf32(v.x); p[1] = f2tf32(v.y);
            p[2] = f2tf32(v.z); p[3] = f2tf32(v.w);
        }
        // ---- stage A: conv weights [o][cc*3+tap] stride 100 ----
        for (int idx = tid; idx < 64 * 96; idx += 256) {
            int o = idx / 96, ck = idx - o * 96;
            sA[o * 100 + ck] = f2tf32(cw[((size_t)(m0 + o) * CIN + c0) * 3 + ck]);
        }
        // ---- stage Ad: downsample weights stride 36 ----
        for (int idx = tid; idx < 64 * 8; idx += 256) {
            int o = idx >> 3, q = idx & 7;
            float4 v = *(const float4*)(dw + (size_t)(m0 + o) * CIN + c0 + q * 4);
            uint32_t* p = sAd + o * 36 + q * 4;
            p[0] = f2tf32(v.x); p[1] = f2tf32(v.y);
            p[2] = f2tf32(v.z); p[3] = f2tf32(v.w);
        }
        __syncthreads();

#pragma unroll
        for (int ks = 0; ks < 4; ks++) {
            const int cb8 = ks * 8;
            uint32_t b[4][2];
#pragma unroll
            for (int tap = 0; tap < 3; tap++) {
#pragma unroll
                for (int nt = 0; nt < 4; nt++) {
                    int ba = laneB + nt * 288 + tap * (DIL * 36) + cb8;
                    b[nt][0] = sB[ba];
                    b[nt][1] = sB[ba + 4];
                }
                uint32_t a[2][4];
#pragma unroll
                for (int mt = 0; mt < 2; mt++) {
                    int orow = mh * 32 + mt * 16 + lr;
                    int ck0 = (cb8 + lc) * 3 + tap;
                    a[mt][0] = sA[orow * 100 + ck0];
                    a[mt][1] = sA[(orow + 8) * 100 + ck0];
                    a[mt][2] = sA[orow * 100 + ck0 + 12];
                    a[mt][3] = sA[(orow + 8) * 100 + ck0 + 12];
                }
#pragma unroll
                for (int mt = 0; mt < 2; mt++)
#pragma unroll
                    for (int nt = 0; nt < 4; nt++)
                        mma8(acc1[mt][nt], a[mt], b[nt]);
            }
            // downsample reuses tap-2 B frags (shift 0 => u = t + 2*DIL)
            uint32_t ad[2][4];
#pragma unroll
            for (int mt = 0; mt < 2; mt++) {
                int orow = mh * 32 + mt * 16 + lr;
                ad[mt][0] = sAd[orow * 36 + cb8 + lc];
                ad[mt][1] = sAd[(orow + 8) * 36 + cb8 + lc];
                ad[mt][2] = sAd[orow * 36 + cb8 + lc + 4];
                ad[mt][3] = sAd[(orow + 8) * 36 + cb8 + lc + 4];
            }
#pragma unroll
            for (int mt = 0; mt < 2; mt++)
#pragma unroll
                for (int nt = 0; nt < 4; nt++)
                    mma8(acc2[mt][nt], ad[mt], b[nt]);
        }
    }

    // ---- epilogue: relu(relu(conv+cb)+down+db), smem transpose, float4 STG ----
    __syncthreads();
    float* sO = (float*)sm;  // [128 padded pos][64 ch] stride 68
#pragma unroll
    for (int mt = 0; mt < 2; mt++) {
        int ob = m0 + mh * 32 + mt * 16 + lr;
        float bc0 = cb[ob], bc1 = cb[ob + 8];
        float bd0 = db[ob], bd1 = db[ob + 8];
#pragma unroll
        for (int nt = 0; nt < 4; nt++) {
#pragma unroll
            for (int r = 0; r < 4; r++) {
                float bc = (r >= 2) ? bc1 : bc0;
                float bd = (r >= 2) ? bd1 : bd0;
                int oo = mh * 32 + mt * 16 + lr + ((r >= 2) ? 8 : 0);
                int po = nq * 32 + nt * 8 + lc * 2 + (r & 1);
                float y = fmaxf(fmaxf(acc1[mt][nt][r] + bc, 0.f) + acc2[mt][nt][r] + bd, 0.f);
                sO[po * 68 + oo] = y;
            }
        }
    }
    __syncthreads();
    for (int idx = tid; idx < 120 * 16; idx += 256) {
        int gi = idx / 480;
        int r = idx - gi * 480;
        int t = r >> 4, q = r & 15;
        float4 v = *(float4*)&sO[(gi * 32 + t) * 68 + q * 4];
        *(float4*)(Xout + (size_t)((g0 + gi) * 30 + t) * COUT + m0 + q * 4) = v;
    }
}

// ---------------- FC ----------------
__global__ void k_prep(const float* __restrict__ fcw, const float* __restrict__ fcb,
                       float* __restrict__ out) {
    int idx = blockIdx.x * blockDim.x + threadIdx.x;
    if (idx < FCO * FCK) {
        int j = idx / FCK, kk = idx % FCK;
        g_fcwT[kk * FCO + j] = fcw[idx];
    }
    if (idx < NB * FCO) out[idx] = fcb[idx % FCO];
}
__global__ void k_fc(float* __restrict__ out) {
    extern __shared__ float sxf[];  // [8][3840]
    const int GF = 8;
    int g0 = blockIdx.x * GF;
    int tid = threadIdx.x;  // 288
    for (int idx = tid; idx < GF * FCK; idx += 288) {
        int g = idx / FCK;
        int rem = idx - g * FCK;
        int pos = rem >> 7, c = rem & 127;
        sxf[g * FCK + c * 30 + pos] = g_X3[((size_t)(g0 + g) * 30 + pos) * 128 + c];
    }
    __syncthreads();
    int j = tid % FCO, q = tid / FCO;
    float acc[GF];
#pragma unroll
    for (int g = 0; g < GF; g++) acc[g] = 0.f;
    int k0 = q * (FCK / 4);
    for (int kk = k0; kk < k0 + FCK / 4; kk++) {
        float wv = g_fcwT[kk * FCO + j];
#pragma unroll
        for (int g = 0; g < GF; g++) acc[g] = fmaf(wv, sxf[g * FCK + kk], acc[g]);
    }
#pragma unroll
    for (int g = 0; g < GF; g++) atomicAdd(&out[(g0 + g) * FCO + j], acc[g]);
}

// ---------------- launch ----------------
extern "C" void kernel_launch(void* const* d_in, const int* in_sizes, int n_in,
                              void* d_out, int out_size) {
    const float* x    = (const float*)d_in[0];
    const void*  ei   = d_in[1];
    const float* gcnw = (const float*)d_in[2];
    const float* gcnb = (const float*)d_in[3];
    const float* cw0  = (const float*)d_in[4];
    const float* cb0  = (const float*)d_in[5];
    const float* dw0  = (const float*)d_in[6];
    const float* db0  = (const float*)d_in[7];
    const float* cw1  = (const float*)d_in[8];
    const float* cb1  = (const float*)d_in[9];
    const float* dw1  = (const float*)d_in[10];
    const float* db1  = (const float*)d_in[11];
    const float* cw2  = (const float*)d_in[12];
    const float* cb2  = (const float*)d_in[13];
    const float* dw2  = (const float*)d_in[14];
    const float* db2  = (const float*)d_in[15];
    const float* fcw  = (const float*)d_in[16];
    const float* fcb  = (const float*)d_in[17];
    float* out = (float*)d_out;

    float *pX1, *pX2, *pX3, *pDeg, *pAcc;
    cudaGetSymbolAddress((void**)&pX1, g_X1);
    cudaGetSymbolAddress((void**)&pX2, g_X2);
    cudaGetSymbolAddress((void**)&pX3, g_X3);
    cudaGetSymbolAddress((void**)&pDeg, g_deg);
    cudaGetSymbolAddress((void**)&pAcc, g_acc);

    cudaMemsetAsync(pDeg, 0, NTOT * sizeof(float));
    cudaMemsetAsync(pAcc, 0, NTOT * 12 * sizeof(float));

    k_linDeg<<<2160, 256>>>(x, gcnw, ei);            // launch 0
    k_scatter<<<NE / 256, 256>>>(ei);                // launch 1
    k_tcn0f<<<NTOT / 32, 128>>>(cw0, cb0, dw0, db0, gcnb);  // launch 2

    constexpr int SM1 = (4 * (32 + 6) * 36 + 64 * 100 + 64 * 36) * 4;
    constexpr int SM2 = (4 * (32 + 18) * 36 + 64 * 100 + 64 * 36) * 4;
    cudaFuncSetAttribute(k_tcnM<128, 512, 3>,
                         cudaFuncAttributeMaxDynamicSharedMemorySize, SM1);
    cudaFuncSetAttribute(k_tcnM<512, 128, 9>,
                         cudaFuncAttributeMaxDynamicSharedMemorySize, SM2);
    k_tcnM<128, 512, 3><<<dim3(8, NB / 4), 256, SM1>>>(pX1, cw1, cb1, dw1, db1, pX2);  // launch 3 -> overall #5, profiled
    k_tcnM<512, 128, 9><<<dim3(2, NB / 4), 256, SM2>>>(pX2, cw2, cb2, dw2, db2, pX3);  // launch 4

    k_prep<<<(FCO * FCK + 255) / 256, 256>>>(fcw, fcb, out);
    cudaFuncSetAttribute(k_fc, cudaFuncAttributeMaxDynamicSharedMemorySize,
                         8 * FCK * (int)sizeof(float));
    k_fc<<<NB / 8, 288, 8 * FCK * (int)sizeof(float)>>>(out);
}

// round 5
// speedup vs baseline: 2.8164x; 1.0226x over previous
#include <cuda_runtime.h>
#include <cstdint>

// ---------------- problem constants ----------------
#define NTOT 61440      // B*30 positions/nodes
#define NB   2048
#define NE   491520
#define FCK  3840       // 128*30
#define FCO  72

// ---------------- scratch ----------------
__device__ float g_h[NTOT * 12];
__device__ float g_deg[NTOT];              // edge-degree (self loop added as +1)
__device__ float g_acc[NTOT * 12];
__device__ float g_X1[(size_t)NTOT * 128]; // [pos][128]
__device__ float g_X2[(size_t)NTOT * 512]; // [pos][512]
__device__ float g_X3[(size_t)NTOT * 128]; // [pos][128]
__device__ float g_fcwT[FCK * FCO];

// ---------------- helpers ----------------
__device__ __forceinline__ uint32_t f2tf32(float f) {
    uint32_t u;
    asm("cvt.rna.tf32.f32 %0, %1;" : "=r"(u) : "f"(f));
    return u;
}
__device__ __forceinline__ void mma8(float* d, const uint32_t* a, const uint32_t* b) {
    asm volatile(
        "mma.sync.aligned.m16n8k8.row.col.f32.tf32.tf32.f32 "
        "{%0,%1,%2,%3}, {%4,%5,%6,%7}, {%8,%9}, {%0,%1,%2,%3};"
        : "+f"(d[0]), "+f"(d[1]), "+f"(d[2]), "+f"(d[3])
        : "r"(a[0]), "r"(a[1]), "r"(a[2]), "r"(a[3]), "r"(b[0]), "r"(b[1]));
}
// channel-pair interleave within groups of 8: (c, c+4) -> adjacent words
__device__ __forceinline__ int permc(int c) {
    return (c & ~7) | ((c & 3) << 1) | ((c >> 2) & 1);
}

// per-block edge-dtype detection (int64 high halves are 0)
__device__ __forceinline__ int detect_is64(const void* ei, int tid) {
    __shared__ int sdet;
    if (tid == 0) sdet = 0;
    __syncthreads();
    if (tid < 64) {
        int v = ((const int*)ei)[2 * tid + 1];
        if (v) atomicOr(&sdet, 1);
    }
    __syncthreads();
    return sdet == 0;
}
__device__ __forceinline__ void load_edge(const void* ei, int e, int is64, int& src, int& dst) {
    if (is64) {
        const long long* p = (const long long*)ei;
        src = (int)p[e]; dst = (int)p[NE + e];
    } else {
        const int* p = (const int*)ei;
        src = p[e]; dst = p[NE + e];
    }
}

// ---------------- GCN: fused lin + degree ----------------
__global__ __launch_bounds__(256) void k_linDeg(
    const float* __restrict__ x, const float* __restrict__ w, const void* ei) {
    int tid = threadIdx.x;
    if (blockIdx.x < 240) {
        __shared__ float sw[144];
        if (tid < 144) sw[tid] = w[tid];
        __syncthreads();
        int n = blockIdx.x * 256 + tid;
        float xv[12];
#pragma unroll
        for (int c = 0; c < 12; c++) xv[c] = x[n * 12 + c];
#pragma unroll
        for (int o = 0; o < 12; o++) {
            float s = 0.f;
#pragma unroll
            for (int c = 0; c < 12; c++) s = fmaf(sw[o * 12 + c], xv[c], s);
            g_h[n * 12 + o] = s;
        }
    } else {
        int is64 = detect_is64(ei, tid);
        int e = (blockIdx.x - 240) * 256 + tid;
        int src, dst;
        load_edge(ei, e, is64, src, dst);
        (void)src;
        atomicAdd(&g_deg[dst], 1.0f);
    }
}

__global__ __launch_bounds__(256) void k_scatter(const void* ei) {
    int tid = threadIdx.x;
    int is64 = detect_is64(ei, tid);
    int e = blockIdx.x * 256 + tid;
    int src, dst;
    load_edge(ei, e, is64, src, dst);
    float norm = rsqrtf(g_deg[src] + 1.0f) * rsqrtf(g_deg[dst] + 1.0f);
    float4 h0 = *(const float4*)(g_h + src * 12);
    float4 h1 = *(const float4*)(g_h + src * 12 + 4);
    float4 h2 = *(const float4*)(g_h + src * 12 + 8);
    float* ad = &g_acc[dst * 12];
    atomicAdd(ad + 0, norm * h0.x);  atomicAdd(ad + 1, norm * h0.y);
    atomicAdd(ad + 2, norm * h0.z);  atomicAdd(ad + 3, norm * h0.w);
    atomicAdd(ad + 4, norm * h1.x);  atomicAdd(ad + 5, norm * h1.y);
    atomicAdd(ad + 6, norm * h1.z);  atomicAdd(ad + 7, norm * h1.w);
    atomicAdd(ad + 8, norm * h2.x);  atomicAdd(ad + 9, norm * h2.y);
    atomicAdd(ad + 10, norm * h2.z); atomicAdd(ad + 11, norm * h2.w);
}

// ---------------- fused gcn_out + TCN block 0 (12 -> 128, dil=1) ----------------
__global__ __launch_bounds__(128) void k_tcn0f(
    const float* __restrict__ cw, const float* __restrict__ cb,
    const float* __restrict__ dw, const float* __restrict__ db,
    const float* __restrict__ gcnb) {
    __shared__ float sx[34][12];
    int tid = threadIdx.x;
    int p0 = blockIdx.x * 32;
    for (int i = tid; i < 34 * 12; i += 128) {
        int r = i / 12, c = i % 12;
        int p = p0 - 2 + r;
        float v = 0.f;
        if (p >= 0) {
            float di = rsqrtf(g_deg[p] + 1.0f);
            v = g_acc[p * 12 + c] + di * di * g_h[p * 12 + c] + gcnb[c];
        }
        sx[r][c] = v;
    }
    __syncthreads();
    int ch = tid;
    float w[36], wd[12];
#pragma unroll
    for (int i = 0; i < 36; i++) w[i] = cw[ch * 36 + i];
#pragma unroll
    for (int i = 0; i < 12; i++) wd[i] = dw[ch * 12 + i];
    float bc = cb[ch], bd = db[ch];
    for (int j = 0; j < 32; j++) {
        int p = p0 + j;
        int t = p % 30;
        float acc = 0.f, accd = 0.f;
#pragma unroll
        for (int k = 0; k < 3; k++) {
            if (t - 2 + k >= 0) {
#pragma unroll
                for (int ci = 0; ci < 12; ci++)
                    acc = fmaf(w[ci * 3 + k], sx[j + k][ci], acc);
            }
        }
#pragma unroll
        for (int ci = 0; ci < 12; ci++) accd = fmaf(wd[ci], sx[j + 2][ci], accd);
        g_X1[(size_t)p * 128 + ch] = fmaxf(fmaxf(acc + bc, 0.f) + accd + bd, 0.f);
    }
}

// ---------------- tf32 mma.sync TCN block, vectorized LDS ----------------
// CTA: 64 out-ch x 4 graphs (N=128 padded). B halo [gi][u][permc(c)] stride 40;
// A [o][tap*32 + permc(c)] stride 104; Ad [o][permc(c)] stride 40.
// All inner-loop fragment k-pairs (c, c+4) are single ld.shared.v2.b32.
template <int CIN, int COUT, int DIL>
__global__ __launch_bounds__(256, 2) void k_tcnM(
    const float* __restrict__ Xin, const float* __restrict__ cw,
    const float* __restrict__ cb, const float* __restrict__ dw,
    const float* __restrict__ db, float* __restrict__ Xout) {
    constexpr int W = 32 + 2 * DIL;
    constexpr int W40 = W * 40;
    extern __shared__ uint32_t sm[];
    uint32_t* sB = sm;                   // 4*W40
    uint32_t* sA = sm + 4 * W40;         // 64*104
    uint32_t* sAd = sA + 64 * 104;       // 64*40

    const int tid = threadIdx.x;
    const int w = tid >> 5, lane = tid & 31;
    const int lr = lane >> 2, lc = lane & 3;
    const int mh = w & 1;                // M half (32 ch)
    const int nq = w >> 1;               // graph within CTA
    const int m0 = blockIdx.x * 64;
    const int g0 = blockIdx.y * 4;

    float acc1[2][4][4], acc2[2][4][4];
#pragma unroll
    for (int mt = 0; mt < 2; mt++)
#pragma unroll
        for (int nt = 0; nt < 4; nt++)
#pragma unroll
            for (int r = 0; r < 4; r++) { acc1[mt][nt][r] = 0.f; acc2[mt][nt][r] = 0.f; }

    const uint32_t* bBase = sB + nq * W40 + lr * 40;
    const int ar0 = mh * 32 + lr;        // A row for mt=0

    for (int c0 = 0; c0 < CIN; c0 += 32) {
        __syncthreads();
        // ---- stage B: halo window per graph; pair-interleaved channel order ----
#pragma unroll
        for (int gi = 0; gi < 4; gi++) {
            for (int idx = tid; idx < W * 8; idx += 256) {
                int u = idx >> 3, q = idx & 7;
                int t = u - 2 * DIL;
                float4 v = make_float4(0.f, 0.f, 0.f, 0.f);
                if (t >= 0 && t < 30)
                    v = *(const float4*)(Xin + (size_t)((g0 + gi) * 30 + t) * CIN + c0 + q * 4);
                uint32_t* p = sB + gi * W40 + u * 40 + ((q >> 1) << 3) + (q & 1);
                p[0] = f2tf32(v.x); p[2] = f2tf32(v.y);
                p[4] = f2tf32(v.z); p[6] = f2tf32(v.w);
            }
        }
        // ---- stage A: conv weights, float4 LDG, layout [o][tap*32+permc(cc)] ----
        for (int idx = tid; idx < 64 * 24; idx += 256) {
            int o = idx / 24, f4 = idx - (idx / 24) * 24;
            float4 v = *(const float4*)(cw + ((size_t)(m0 + o) * CIN + c0) * 3 + f4 * 4);
            float vv[4] = {v.x, v.y, v.z, v.w};
#pragma unroll
            for (int j = 0; j < 4; j++) {
                int li = f4 * 4 + j;
                int cc = li / 3, tap = li - cc * 3;
                sA[o * 104 + tap * 32 + permc(cc)] = f2tf32(vv[j]);
            }
        }
        // ---- stage Ad: downsample weights, pair-interleaved ----
        for (int idx = tid; idx < 64 * 8; idx += 256) {
            int o = idx >> 3, q = idx & 7;
            float4 v = *(const float4*)(dw + (size_t)(m0 + o) * CIN + c0 + q * 4);
            uint32_t* p = sAd + o * 40 + ((q >> 1) << 3) + (q & 1);
            p[0] = f2tf32(v.x); p[2] = f2tf32(v.y);
            p[4] = f2tf32(v.z); p[6] = f2tf32(v.w);
        }
        __syncthreads();

#pragma unroll
        for (int ks = 0; ks < 4; ks++) {
            const int kc = ks * 8 + lc * 2;
            uint32_t b[4][2];
#pragma unroll
            for (int tap = 0; tap < 3; tap++) {
#pragma unroll
                for (int nt = 0; nt < 4; nt++) {
                    uint2 bb = *(const uint2*)(bBase + nt * 320 + tap * (DIL * 40) + kc);
                    b[nt][0] = bb.x; b[nt][1] = bb.y;
                }
                uint32_t a[2][4];
#pragma unroll
                for (int mt = 0; mt < 2; mt++) {
                    int ar = ar0 + mt * 16;
                    uint2 a0 = *(const uint2*)(sA + ar * 104 + tap * 32 + kc);
                    uint2 a1 = *(const uint2*)(sA + (ar + 8) * 104 + tap * 32 + kc);
                    a[mt][0] = a0.x; a[mt][1] = a1.x; a[mt][2] = a0.y; a[mt][3] = a1.y;
                }
#pragma unroll
                for (int mt = 0; mt < 2; mt++)
#pragma unroll
                    for (int nt = 0; nt < 4; nt++)
                        mma8(acc1[mt][nt], a[mt], b[nt]);
            }
            // downsample reuses tap-2 B frags (u = t + 2*DIL)
            uint32_t ad[2][4];
#pragma unroll
            for (int mt = 0; mt < 2; mt++) {
                int ar = ar0 + mt * 16;
                uint2 d0 = *(const uint2*)(sAd + ar * 40 + kc);
                uint2 d1 = *(const uint2*)(sAd + (ar + 8) * 40 + kc);
                ad[mt][0] = d0.x; ad[mt][1] = d1.x; ad[mt][2] = d0.y; ad[mt][3] = d1.y;
            }
#pragma unroll
            for (int mt = 0; mt < 2; mt++)
#pragma unroll
                for (int nt = 0; nt < 4; nt++)
                    mma8(acc2[mt][nt], ad[mt], b[nt]);
        }
    }

    // ---- epilogue: relu(relu(conv+cb)+down+db), smem transpose, float4 STG ----
    __syncthreads();
    float* sO = (float*)sm;  // [128 padded pos][64 ch] stride 68
#pragma unroll
    for (int mt = 0; mt < 2; mt++) {
        int ob = m0 + mh * 32 + mt * 16 + lr;
        float bc0 = cb[ob], bc1 = cb[ob + 8];
        float bd0 = db[ob], bd1 = db[ob + 8];
#pragma unroll
        for (int nt = 0; nt < 4; nt++) {
#pragma unroll
            for (int r = 0; r < 4; r++) {
                float bc = (r >= 2) ? bc1 : bc0;
                float bd = (r >= 2) ? bd1 : bd0;
                int oo = mh * 32 + mt * 16 + lr + ((r >= 2) ? 8 : 0);
                int po = nq * 32 + nt * 8 + lc * 2 + (r & 1);
                float y = fmaxf(fmaxf(acc1[mt][nt][r] + bc, 0.f) + acc2[mt][nt][r] + bd, 0.f);
                sO[po * 68 + oo] = y;
            }
        }
    }
    __syncthreads();
#pragma unroll
    for (int gi = 0; gi < 4; gi++) {
        for (int idx = tid; idx < 480; idx += 256) {
            int t = idx >> 4, q = idx & 15;
            float4 v = *(float4*)&sO[(gi * 32 + t) * 68 + q * 4];
            *(float4*)(Xout + (size_t)((g0 + gi) * 30 + t) * COUT + m0 + q * 4) = v;
        }
    }
}

// ---------------- FC ----------------
__global__ void k_prep(const float* __restrict__ fcw, const float* __restrict__ fcb,
                       float* __restrict__ out) {
    int idx = blockIdx.x * blockDim.x + threadIdx.x;
    if (idx < FCO * FCK) {
        int j = idx / FCK, kk = idx % FCK;
        g_fcwT[kk * FCO + j] = fcw[idx];
    }
    if (idx < NB * FCO) out[idx] = fcb[idx % FCO];
}
__global__ void k_fc(float* __restrict__ out) {
    extern __shared__ float sxf[];  // [8][3840]
    const int GF = 8;
    int g0 = blockIdx.x * GF;
    int tid = threadIdx.x;  // 288
    for (int idx = tid; idx < GF * FCK; idx += 288) {
        int g = idx / FCK;
        int rem = idx - g * FCK;
        int pos = rem >> 7, c = rem & 127;
        sxf[g * FCK + c * 30 + pos] = g_X3[((size_t)(g0 + g) * 30 + pos) * 128 + c];
    }
    __syncthreads();
    int j = tid % FCO, q = tid / FCO;
    float acc[GF];
#pragma unroll
    for (int g = 0; g < GF; g++) acc[g] = 0.f;
    int k0 = q * (FCK / 4);
    for (int kk = k0; kk < k0 + FCK / 4; kk++) {
        float wv = g_fcwT[kk * FCO + j];
#pragma unroll
        for (int g = 0; g < GF; g++) acc[g] = fmaf(wv, sxf[g * FCK + kk], acc[g]);
    }
#pragma unroll
    for (int g = 0; g < GF; g++) atomicAdd(&out[(g0 + g) * FCO + j], acc[g]);
}

// ---------------- launch ----------------
extern "C" void kernel_launch(void* const* d_in, const int* in_sizes, int n_in,
                              void* d_out, int out_size) {
    const float* x    = (const float*)d_in[0];
    const void*  ei   = d_in[1];
    const float* gcnw = (const float*)d_in[2];
    const float* gcnb = (const float*)d_in[3];
    const float* cw0  = (const float*)d_in[4];
    const float* cb0  = (const float*)d_in[5];
    const float* dw0  = (const float*)d_in[6];
    const float* db0  = (const float*)d_in[7];
    const float* cw1  = (const float*)d_in[8];
    const float* cb1  = (const float*)d_in[9];
    const float* dw1  = (const float*)d_in[10];
    const float* db1  = (const float*)d_in[11];
    const float* cw2  = (const float*)d_in[12];
    const float* cb2  = (const float*)d_in[13];
    const float* dw2  = (const float*)d_in[14];
    const float* db2  = (const float*)d_in[15];
    const float* fcw  = (const float*)d_in[16];
    const float* fcb  = (const float*)d_in[17];
    float* out = (float*)d_out;

    float *pX1, *pX2, *pX3, *pDeg, *pAcc;
    cudaGetSymbolAddress((void**)&pX1, g_X1);
    cudaGetSymbolAddress((void**)&pX2, g_X2);
    cudaGetSymbolAddress((void**)&pX3, g_X3);
    cudaGetSymbolAddress((void**)&pDeg, g_deg);
    cudaGetSymbolAddress((void**)&pAcc, g_acc);

    cudaMemsetAsync(pDeg, 0, NTOT * sizeof(float));
    cudaMemsetAsync(pAcc, 0, NTOT * 12 * sizeof(float));

    k_linDeg<<<2160, 256>>>(x, gcnw, ei);
    k_scatter<<<NE / 256, 256>>>(ei);
    k_tcn0f<<<NTOT / 32, 128>>>(cw0, cb0, dw0, db0, gcnb);

    constexpr int SM1 = (4 * (32 + 6) * 40 + 64 * 104 + 64 * 40) * 4;
    constexpr int SM2 = (4 * (32 + 18) * 40 + 64 * 104 + 64 * 40) * 4;
    cudaFuncSetAttribute(k_tcnM<128, 512, 3>,
                         cudaFuncAttributeMaxDynamicSharedMemorySize, SM1);
    cudaFuncSetAttribute(k_tcnM<512, 128, 9>,
                         cudaFuncAttributeMaxDynamicSharedMemorySize, SM2);
    k_tcnM<128, 512, 3><<<dim3(8, NB / 4), 256, SM1>>>(pX1, cw1, cb1, dw1, db1, pX2);
    k_tcnM<512, 128, 9><<<dim3(2, NB / 4), 256, SM2>>>(pX2, cw2, cb2, dw2, db2, pX3);

    k_prep<<<(FCO * FCK + 255) / 256, 256>>>(fcw, fcb, out);
    cudaFuncSetAttribute(k_fc, cudaFuncAttributeMaxDynamicSharedMemorySize,
                         8 * FCK * (int)sizeof(float));
    k_fc<<<NB / 8, 288, 8 * FCK * (int)sizeof(float)>>>(out);
}

// round 6
// speedup vs baseline: 6.0217x; 2.1380x over previous
#include <cuda_runtime.h>
#include <cuda_fp16.h>
#include <cstdint>

// ---------------- problem constants ----------------
#define NTOT 61440      // B*30 positions/nodes
#define NB   2048
#define NE   491520
#define FCK  3840       // 128*30
#define FCO  72

// ---------------- scratch ----------------
__device__ float g_h[NTOT * 12];
__device__ float g_deg[NTOT];
__device__ float g_acc[NTOT * 12];
__device__ __align__(256) __half g_X1h[(size_t)NTOT * 128];
__device__ __align__(256) __half g_X2h[(size_t)NTOT * 512];
__device__ float g_X3[(size_t)NTOT * 128];
__device__ float g_fcwT[FCK * FCO];
// pre-laid-out fp16 weights: wC [mblk][chunk][o(64)][tap*32+cc], wD [mblk][chunk][o][32]
__device__ __align__(256) __half g_wC1[8 * 4 * 64 * 96];
__device__ __align__(256) __half g_wD1[8 * 4 * 64 * 32];
__device__ __align__(256) __half g_wC2[2 * 16 * 64 * 96];
__device__ __align__(256) __half g_wD2[2 * 16 * 64 * 32];

// ---------------- PTX helpers ----------------
#define CP16(d, s) asm volatile("cp.async.cg.shared.global [%0], [%1], 16;" :: "r"(d), "l"(s))
#define CP_COMMIT() asm volatile("cp.async.commit_group;" ::: "memory")
#define CP_WAIT1() asm volatile("cp.async.wait_group 1;" ::: "memory")
#define CP_WAIT0() asm volatile("cp.async.wait_group 0;" ::: "memory")
#define LDMX4(r0, r1, r2, r3, a) \
    asm volatile("ldmatrix.sync.aligned.m8n8.x4.shared.b16 {%0,%1,%2,%3}, [%4];" \
        : "=r"(r0), "=r"(r1), "=r"(r2), "=r"(r3) : "r"(a))

__device__ __forceinline__ void mma16(float* d, const uint32_t* a, const uint32_t* b) {
    asm volatile(
        "mma.sync.aligned.m16n8k16.row.col.f32.f16.f16.f32 "
        "{%0,%1,%2,%3}, {%4,%5,%6,%7}, {%8,%9}, {%0,%1,%2,%3};"
        : "+f"(d[0]), "+f"(d[1]), "+f"(d[2]), "+f"(d[3])
        : "r"(a[0]), "r"(a[1]), "r"(a[2]), "r"(a[3]), "r"(b[0]), "r"(b[1]));
}

// ---------------- edge dtype detect ----------------
__device__ __forceinline__ int detect_is64(const void* ei, int tid) {
    __shared__ int sdet;
    if (tid == 0) sdet = 0;
    __syncthreads();
    if (tid < 64) {
        int v = ((const int*)ei)[2 * tid + 1];
        if (v) atomicOr(&sdet, 1);
    }
    __syncthreads();
    return sdet == 0;
}
__device__ __forceinline__ void load_edge(const void* ei, int e, int is64, int& src, int& dst) {
    if (is64) {
        const long long* p = (const long long*)ei;
        src = (int)p[e]; dst = (int)p[NE + e];
    } else {
        const int* p = (const int*)ei;
        src = p[e]; dst = p[NE + e];
    }
}

// ---------------- mega prep kernel: GCN linear + degree + all weight prep ----------------
__global__ __launch_bounds__(256) void k_linDeg(
    const float* __restrict__ x, const float* __restrict__ w, const void* ei,
    const float* __restrict__ cw1, const float* __restrict__ dw1,
    const float* __restrict__ cw2, const float* __restrict__ dw2,
    const float* __restrict__ fcw, const float* __restrict__ fcb,
    float* __restrict__ out) {
    int tid = threadIdx.x;
    int b = blockIdx.x;
    if (b < 240) {
        __shared__ float sw[144];
        if (tid < 144) sw[tid] = w[tid];
        __syncthreads();
        int n = b * 256 + tid;
        float xv[12];
#pragma unroll
        for (int c = 0; c < 12; c++) xv[c] = x[n * 12 + c];
#pragma unroll
        for (int o = 0; o < 12; o++) {
            float s = 0.f;
#pragma unroll
            for (int c = 0; c < 12; c++) s = fmaf(sw[o * 12 + c], xv[c], s);
            g_h[n * 12 + o] = s;
        }
    } else if (b < 2160) {
        int is64 = detect_is64(ei, tid);
        int e = (b - 240) * 256 + tid;
        int src, dst;
        load_edge(ei, e, is64, src, dst);
        (void)src;
        atomicAdd(&g_deg[dst], 1.0f);
    } else if (b < 2928) {           // conv1 -> g_wC1
        int d = (b - 2160) * 256 + tid;
        int r = d / 96, rem = d - r * 96;
        int mb = r >> 8, ch = (r >> 6) & 3, o = r & 63;
        int tap = rem >> 5, cc = rem & 31;
        g_wC1[d] = __float2half(cw1[((mb * 64 + o) * 128 + ch * 32 + cc) * 3 + tap]);
    } else if (b < 3184) {           // down1 -> g_wD1
        int d = (b - 2928) * 256 + tid;
        int r = d >> 5, cc = d & 31;
        int mb = r >> 8, ch = (r >> 6) & 3, o = r & 63;
        g_wD1[d] = __float2half(dw1[(mb * 64 + o) * 128 + ch * 32 + cc]);
    } else if (b < 3952) {           // conv2 -> g_wC2
        int d = (b - 3184) * 256 + tid;
        int r = d / 96, rem = d - r * 96;
        int mb = r >> 10, ch = (r >> 6) & 15, o = r & 63;
        int tap = rem >> 5, cc = rem & 31;
        g_wC2[d] = __float2half(cw2[((mb * 64 + o) * 512 + ch * 32 + cc) * 3 + tap]);
    } else if (b < 4208) {           // down2 -> g_wD2
        int d = (b - 3952) * 256 + tid;
        int r = d >> 5, cc = d & 31;
        int mb = r >> 10, ch = (r >> 6) & 15, o = r & 63;
        g_wD2[d] = __float2half(dw2[(mb * 64 + o) * 512 + ch * 32 + cc]);
    } else if (b < 5288) {           // fc transpose
        int idx = (b - 4208) * 256 + tid;
        if (idx < FCO * FCK) {
            int j = idx / FCK, kk = idx - (idx / FCK) * FCK;
            g_fcwT[kk * FCO + j] = fcw[idx];
        }
    } else {                         // out bias init
        int idx = (b - 5288) * 256 + tid;
        if (idx < NB * FCO) out[idx] = fcb[idx % FCO];
    }
}

__global__ __launch_bounds__(256) void k_scatter(const void* ei) {
    int tid = threadIdx.x;
    int is64 = detect_is64(ei, tid);
    int e = blockIdx.x * 256 + tid;
    int src, dst;
    load_edge(ei, e, is64, src, dst);
    float norm = rsqrtf(g_deg[src] + 1.0f) * rsqrtf(g_deg[dst] + 1.0f);
    float4 h0 = *(const float4*)(g_h + src * 12);
    float4 h1 = *(const float4*)(g_h + src * 12 + 4);
    float4 h2 = *(const float4*)(g_h + src * 12 + 8);
    float* ad = &g_acc[dst * 12];
    atomicAdd(ad + 0, norm * h0.x);  atomicAdd(ad + 1, norm * h0.y);
    atomicAdd(ad + 2, norm * h0.z);  atomicAdd(ad + 3, norm * h0.w);
    atomicAdd(ad + 4, norm * h1.x);  atomicAdd(ad + 5, norm * h1.y);
    atomicAdd(ad + 6, norm * h1.z);  atomicAdd(ad + 7, norm * h1.w);
    atomicAdd(ad + 8, norm * h2.x);  atomicAdd(ad + 9, norm * h2.y);
    atomicAdd(ad + 10, norm * h2.z); atomicAdd(ad + 11, norm * h2.w);
}

// ---------------- fused gcn_out + TCN block 0 (12 -> 128, dil=1), fp16 out ----------------
__global__ __launch_bounds__(128) void k_tcn0f(
    const float* __restrict__ cw, const float* __restrict__ cb,
    const float* __restrict__ dw, const float* __restrict__ db,
    const float* __restrict__ gcnb) {
    __shared__ float sx[34][12];
    int tid = threadIdx.x;
    int p0 = blockIdx.x * 32;
    for (int i = tid; i < 34 * 12; i += 128) {
        int r = i / 12, c = i % 12;
        int p = p0 - 2 + r;
        float v = 0.f;
        if (p >= 0) {
            float di = rsqrtf(g_deg[p] + 1.0f);
            v = g_acc[p * 12 + c] + di * di * g_h[p * 12 + c] + gcnb[c];
        }
        sx[r][c] = v;
    }
    __syncthreads();
    int ch = tid;
    float w[36], wd[12];
#pragma unroll
    for (int i = 0; i < 36; i++) w[i] = cw[ch * 36 + i];
#pragma unroll
    for (int i = 0; i < 12; i++) wd[i] = dw[ch * 12 + i];
    float bc = cb[ch], bd = db[ch];
    for (int j = 0; j < 32; j++) {
        int p = p0 + j;
        int t = p % 30;
        float acc = 0.f, accd = 0.f;
#pragma unroll
        for (int k = 0; k < 3; k++) {
            if (t - 2 + k >= 0) {
#pragma unroll
                for (int ci = 0; ci < 12; ci++)
                    acc = fmaf(w[ci * 3 + k], sx[j + k][ci], acc);
            }
        }
#pragma unroll
        for (int ci = 0; ci < 12; ci++) accd = fmaf(wd[ci], sx[j + 2][ci], accd);
        g_X1h[(size_t)p * 128 + ch] =
            __float2half(fmaxf(fmaxf(acc + bc, 0.f) + accd + bd, 0.f));
    }
}

// ---------------- fp16 mma TCN block: cp.async pipeline + ldmatrix ----------------
// CTA: 64 out-ch x 4 graphs. smem (halves): B 2x[4][W][40], A 2x[64][104], Ad 2x[64][40].
// strides 80B/208B -> conflict-free ldmatrix. Double-buffered cp.async staging.
template <int CIN, int COUT, int DIL, int NCH, bool OUTH>
__global__ __launch_bounds__(256, 2) void k_tcnH(
    const __half* __restrict__ Xin, const __half* __restrict__ wC,
    const __half* __restrict__ wD, const float* __restrict__ cb,
    const float* __restrict__ db, void* __restrict__ XoutV) {
    constexpr int W = 32 + 2 * DIL;
    constexpr int BBUF = 4 * W * 40;          // halves per B buffer
    constexpr int ABUF = 64 * 104;
    constexpr int DBUF = 64 * 40;
    extern __shared__ __half smh[];
    const uint32_t smem0 = (uint32_t)__cvta_generic_to_shared(smh);
    const uint32_t bSec = smem0;
    const uint32_t aSec = smem0 + 2 * BBUF * 2;
    const uint32_t dSec = aSec + 2 * ABUF * 2;

    const int tid = threadIdx.x;
    const int wrp = tid >> 5, lane = tid & 31;
    const int lr = lane >> 2, lc = lane & 3;
    const int l8 = lane & 7, s1 = (lane >> 3) & 1, s2 = lane >> 4;
    const int mh = wrp & 1;          // M half (32 out-ch)
    const int nq = wrp >> 1;         // graph within CTA
    const int mb = blockIdx.x;
    const int m0 = mb * 64;
    const int g0 = blockIdx.y * 4;

    // zero halo rows of both B buffers
    {
        constexpr int ZR = 2 * DIL + 2;
        uint4 z = make_uint4(0, 0, 0, 0);
        for (int idx = tid; idx < 2 * 4 * ZR * 5; idx += 256) {
            int bufg = idx / (ZR * 5);
            int r = idx - bufg * (ZR * 5);
            int zr = r / 5, pc = r - (r / 5) * 5;
            int u = (zr < 2 * DIL) ? zr : (30 + zr);
            int buf = bufg >> 2, gi = bufg & 3;
            *(uint4*)(smh + buf * BBUF + (gi * W + u) * 40 + pc * 8) = z;
        }
    }

    auto stage = [&](int chk, int buf) {
        // B: 4 graphs x 30 rows x 4x16B
        uint32_t bD = bSec + buf * (BBUF * 2);
        for (int idx = tid; idx < 480; idx += 256) {
            int gi = idx / 120;
            int r = idx - gi * 120;
            int t = r >> 2, pc = r & 3;
            uint32_t dst = bD + (gi * W + t + 2 * DIL) * 80 + pc * 16;
            const __half* src = Xin + ((size_t)(g0 + gi) * 30 + t) * CIN + chk * 32 + pc * 8;
            CP16(dst, src);
        }
        // A: 64 rows x 12x16B
        uint32_t aD = aSec + buf * (ABUF * 2);
        const __half* srcA = wC + ((size_t)(mb * NCH + chk) * 64) * 96;
        for (int idx = tid; idx < 768; idx += 256) {
            int o = idx / 12, pc = idx - (idx / 12) * 12;
            CP16(aD + o * 208 + pc * 16, srcA + o * 96 + pc * 8);
        }
        // Ad: 64 rows x 4x16B
        uint32_t dD = dSec + buf * (DBUF * 2);
        const __half* srcD = wD + ((size_t)(mb * NCH + chk) * 64) * 32;
        {
            int o = tid >> 2, pc = tid & 3;
            if (tid < 256) CP16(dD + o * 80 + pc * 16, srcD + o * 32 + pc * 8);
        }
        CP_COMMIT();
    };

    float acc1[2][4][4], acc2[2][4][4];
#pragma unroll
    for (int mt = 0; mt < 2; mt++)
#pragma unroll
        for (int nt = 0; nt < 4; nt++)
#pragma unroll
            for (int r = 0; r < 4; r++) { acc1[mt][nt][r] = 0.f; acc2[mt][nt][r] = 0.f; }

    stage(0, 0);
    stage(1, 1);

    for (int chk = 0; chk < NCH; chk++) {
        const int buf = chk & 1;
        if (chk + 1 < NCH) { CP_WAIT1(); } else { CP_WAIT0(); }
        __syncthreads();

        const uint32_t bRow = bSec + buf * (BBUF * 2) + nq * (W * 80);
        const uint32_t aB = aSec + buf * (ABUF * 2);
        const uint32_t dB = dSec + buf * (DBUF * 2);

#pragma unroll
        for (int kh = 0; kh < 2; kh++) {
            const uint32_t kb = kh * 32;  // k-half byte offset
#pragma unroll
            for (int tap = 0; tap < 3; tap++) {
                // B frags: 2x ldmatrix.x4 -> bf[nt][2]
                uint32_t bf[4][2];
#pragma unroll
                for (int pr = 0; pr < 2; pr++) {
                    uint32_t ba = bRow +
                        (tap * DIL + (pr * 2 + s2) * 8 + l8) * 80 + kb + s1 * 16;
                    LDMX4(bf[pr * 2][0], bf[pr * 2][1], bf[pr * 2 + 1][0], bf[pr * 2 + 1][1], ba);
                }
                // A frags: 2x ldmatrix.x4 -> af[mt][4]
                uint32_t af[2][4];
#pragma unroll
                for (int mt = 0; mt < 2; mt++) {
                    uint32_t aa = aB + (mh * 32 + mt * 16 + s1 * 8 + l8) * 208 +
                                  tap * 64 + kb + s2 * 16;
                    LDMX4(af[mt][0], af[mt][1], af[mt][2], af[mt][3], aa);
                }
#pragma unroll
                for (int mt = 0; mt < 2; mt++)
#pragma unroll
                    for (int nt = 0; nt < 4; nt++)
                        mma16(acc1[mt][nt], af[mt], bf[nt]);
                if (tap == 2) {
                    uint32_t df[2][4];
#pragma unroll
                    for (int mt = 0; mt < 2; mt++) {
                        uint32_t da = dB + (mh * 32 + mt * 16 + s1 * 8 + l8) * 80 +
                                      kb + s2 * 16;
                        LDMX4(df[mt][0], df[mt][1], df[mt][2], df[mt][3], da);
                    }
#pragma unroll
                    for (int mt = 0; mt < 2; mt++)
#pragma unroll
                        for (int nt = 0; nt < 4; nt++)
                            mma16(acc2[mt][nt], df[mt], bf[nt]);
                }
            }
        }
        __syncthreads();
        if (chk + 2 < NCH) stage(chk + 2, buf);
    }

    // ---- epilogue: relu(relu(conv+cb)+down+db); smem transpose; vector STG ----
    float* sO = (float*)smh;  // [128 padded pos][64 ch] stride 68
#pragma unroll
    for (int mt = 0; mt < 2; mt++) {
        int ob = m0 + mh * 32 + mt * 16 + lr;
        float bc0 = cb[ob], bc1 = cb[ob + 8];
        float bd0 = db[ob], bd1 = db[ob + 8];
#pragma unroll
        for (int nt = 0; nt < 4; nt++) {
#pragma unroll
            for (int r = 0; r < 4; r++) {
                float bc = (r >= 2) ? bc1 : bc0;
                float bd = (r >= 2) ? bd1 : bd0;
                int oo = mh * 32 + mt * 16 + lr + ((r >= 2) ? 8 : 0);
                int po = nq * 32 + nt * 8 + lc * 2 + (r & 1);
                float y = fmaxf(fmaxf(acc1[mt][nt][r] + bc, 0.f) + acc2[mt][nt][r] + bd, 0.f);
                sO[po * 68 + oo] = y;
            }
        }
    }
    __syncthreads();
#pragma unroll
    for (int gi = 0; gi < 4; gi++) {
        for (int idx = tid; idx < 480; idx += 256) {
            int t = idx >> 4, q = idx & 15;
            float4 v = *(float4*)&sO[(gi * 32 + t) * 68 + q * 4];
            size_t off = (size_t)((g0 + gi) * 30 + t) * COUT + m0 + q * 4;
            if (OUTH) {
                __half2 h0 = __floats2half2_rn(v.x, v.y);
                __half2 h1 = __floats2half2_rn(v.z, v.w);
                uint2 u;
                u.x = *(uint32_t*)&h0; u.y = *(uint32_t*)&h1;
                *(uint2*)((__half*)XoutV + off) = u;
            } else {
                *(float4*)((float*)XoutV + off) = v;
            }
        }
    }
}

// ---------------- FC ----------------
__global__ void k_fc(float* __restrict__ out) {
    extern __shared__ float sxf[];  // [8][3840]
    const int GF = 8;
    int g0 = blockIdx.x * GF;
    int tid = threadIdx.x;  // 288
    for (int idx = tid; idx < GF * FCK; idx += 288) {
        int g = idx / FCK;
        int rem = idx - g * FCK;
        int pos = rem >> 7, c = rem & 127;
        sxf[g * FCK + c * 30 + pos] = g_X3[((size_t)(g0 + g) * 30 + pos) * 128 + c];
    }
    __syncthreads();
    int j = tid % FCO, q = tid / FCO;
    float acc[GF];
#pragma unroll
    for (int g = 0; g < GF; g++) acc[g] = 0.f;
    int k0 = q * (FCK / 4);
    for (int kk = k0; kk < k0 + FCK / 4; kk++) {
        float wv = g_fcwT[kk * FCO + j];
#pragma unroll
        for (int g = 0; g < GF; g++) acc[g] = fmaf(wv, sxf[g * FCK + kk], acc[g]);
    }
#pragma unroll
    for (int g = 0; g < GF; g++) atomicAdd(&out[(g0 + g) * FCO + j], acc[g]);
}

// ---------------- launch ----------------
extern "C" void kernel_launch(void* const* d_in, const int* in_sizes, int n_in,
                              void* d_out, int out_size) {
    const float* x    = (const float*)d_in[0];
    const void*  ei   = d_in[1];
    const float* gcnw = (const float*)d_in[2];
    const float* gcnb = (const float*)d_in[3];
    const float* cw0  = (const float*)d_in[4];
    const float* cb0  = (const float*)d_in[5];
    const float* dw0  = (const float*)d_in[6];
    const float* db0  = (const float*)d_in[7];
    const float* cw1  = (const float*)d_in[8];
    const float* cb1  = (const float*)d_in[9];
    const float* dw1  = (const float*)d_in[10];
    const float* db1  = (const float*)d_in[11];
    const float* cw2  = (const float*)d_in[12];
    const float* cb2  = (const float*)d_in[13];
    const float* dw2  = (const float*)d_in[14];
    const float* db2  = (const float*)d_in[15];
    const float* fcw  = (const float*)d_in[16];
    const float* fcb  = (const float*)d_in[17];
    float* out = (float*)d_out;

    void *pX1h, *pX2h, *pX3, *pDeg, *pAcc, *pWC1, *pWD1, *pWC2, *pWD2;
    cudaGetSymbolAddress(&pX1h, g_X1h);
    cudaGetSymbolAddress(&pX2h, g_X2h);
    cudaGetSymbolAddress(&pX3, g_X3);
    cudaGetSymbolAddress(&pDeg, g_deg);
    cudaGetSymbolAddress(&pAcc, g_acc);
    cudaGetSymbolAddress(&pWC1, g_wC1);
    cudaGetSymbolAddress(&pWD1, g_wD1);
    cudaGetSymbolAddress(&pWC2, g_wC2);
    cudaGetSymbolAddress(&pWD2, g_wD2);

    cudaMemsetAsync(pDeg, 0, NTOT * sizeof(float));
    cudaMemsetAsync(pAcc, 0, NTOT * 12 * sizeof(float));

    k_linDeg<<<5864, 256>>>(x, gcnw, ei, cw1, dw1, cw2, dw2, fcw, fcb, out);
    k_scatter<<<NE / 256, 256>>>(ei);
    k_tcn0f<<<NTOT / 32, 128>>>(cw0, cb0, dw0, db0, gcnb);

    constexpr int SM1 = (2 * 4 * 38 * 40 + 2 * 64 * 104 + 2 * 64 * 40) * 2;
    constexpr int SM2 = (2 * 4 * 50 * 40 + 2 * 64 * 104 + 2 * 64 * 40) * 2;
    cudaFuncSetAttribute((const void*)k_tcnH<128, 512, 3, 4, true>,
                         cudaFuncAttributeMaxDynamicSharedMemorySize, SM1);
    cudaFuncSetAttribute((const void*)k_tcnH<512, 128, 9, 16, false>,
                         cudaFuncAttributeMaxDynamicSharedMemorySize, SM2);
    k_tcnH<128, 512, 3, 4, true><<<dim3(8, NB / 4), 256, SM1>>>(
        (const __half*)pX1h, (const __half*)pWC1, (const __half*)pWD1, cb1, db1, pX2h);
    k_tcnH<512, 128, 9, 16, false><<<dim3(2, NB / 4), 256, SM2>>>(
        (const __half*)pX2h, (const __half*)pWC2, (const __half*)pWD2, cb2, db2, pX3);

    cudaFuncSetAttribute(k_fc, cudaFuncAttributeMaxDynamicSharedMemorySize,
                         8 * FCK * (int)sizeof(float));
    k_fc<<<NB / 8, 288, 8 * FCK * (int)sizeof(float)>>>(out);
}

// round 7
// speedup vs baseline: 8.9294x; 1.4829x over previous
#include <cuda_runtime.h>
#include <cuda_fp16.h>
#include <cstdint>

// ---------------- problem constants ----------------
#define NTOT 61440      // B*30 positions/nodes
#define NB   2048
#define NE   491520
#define FCO  72

// ---------------- scratch ----------------
__device__ float g_h[NTOT * 12];
__device__ float g_deg[NTOT];
__device__ float g_acc[NTOT * 12];
__device__ __align__(256) __half g_X1h[(size_t)NTOT * 128];
__device__ __align__(256) __half g_X2h[(size_t)NTOT * 512];
__device__ __align__(256) __half g_X3T[(size_t)NB * 3840];  // [g][c*30+t]
__device__ __align__(256) __half g_fcwH[FCO * 3840];
// pre-laid-out fp16 weights
__device__ __align__(256) __half g_wC1[8 * 4 * 64 * 96];
__device__ __align__(256) __half g_wD1[8 * 4 * 64 * 32];
__device__ __align__(256) __half g_wC2[2 * 16 * 64 * 96];
__device__ __align__(256) __half g_wD2[2 * 16 * 64 * 32];

// ---------------- PTX helpers ----------------
#define CP16(d, s) asm volatile("cp.async.cg.shared.global [%0], [%1], 16;" :: "r"(d), "l"(s))
#define CP16Z(d, s) asm volatile("cp.async.cg.shared.global [%0], [%1], 16, 0;" :: "r"(d), "l"(s))
#define CP_COMMIT() asm volatile("cp.async.commit_group;" ::: "memory")
#define CP_WAIT1() asm volatile("cp.async.wait_group 1;" ::: "memory")
#define CP_WAIT0() asm volatile("cp.async.wait_group 0;" ::: "memory")
#define LDMX4(r0, r1, r2, r3, a) \
    asm volatile("ldmatrix.sync.aligned.m8n8.x4.shared.b16 {%0,%1,%2,%3}, [%4];" \
        : "=r"(r0), "=r"(r1), "=r"(r2), "=r"(r3) : "r"(a))

__device__ __forceinline__ void mma16(float* d, const uint32_t* a, const uint32_t* b) {
    asm volatile(
        "mma.sync.aligned.m16n8k16.row.col.f32.f16.f16.f32 "
        "{%0,%1,%2,%3}, {%4,%5,%6,%7}, {%8,%9}, {%0,%1,%2,%3};"
        : "+f"(d[0]), "+f"(d[1]), "+f"(d[2]), "+f"(d[3])
        : "r"(a[0]), "r"(a[1]), "r"(a[2]), "r"(a[3]), "r"(b[0]), "r"(b[1]));
}

// ---------------- edge dtype detect ----------------
__device__ __forceinline__ int detect_is64(const void* ei, int tid) {
    __shared__ int sdet;
    if (tid == 0) sdet = 0;
    __syncthreads();
    if (tid < 64) {
        int v = ((const int*)ei)[2 * tid + 1];
        if (v) atomicOr(&sdet, 1);
    }
    __syncthreads();
    return sdet == 0;
}
__device__ __forceinline__ void load_edge(const void* ei, int e, int is64, int& src, int& dst) {
    if (is64) {
        const long long* p = (const long long*)ei;
        src = (int)p[e]; dst = (int)p[NE + e];
    } else {
        const int* p = (const int*)ei;
        src = p[e]; dst = p[NE + e];
    }
}

// ---------------- mega prep kernel ----------------
__global__ __launch_bounds__(256) void k_linDeg(
    const float* __restrict__ x, const float* __restrict__ w, const void* ei,
    const float* __restrict__ cw1, const float* __restrict__ dw1,
    const float* __restrict__ cw2, const float* __restrict__ dw2,
    const float* __restrict__ fcw) {
    int tid = threadIdx.x;
    int b = blockIdx.x;
    if (b < 240) {
        __shared__ float sw[144];
        if (tid < 144) sw[tid] = w[tid];
        __syncthreads();
        int n = b * 256 + tid;
        float xv[12];
#pragma unroll
        for (int c = 0; c < 12; c++) xv[c] = x[n * 12 + c];
#pragma unroll
        for (int o = 0; o < 12; o++) {
            float s = 0.f;
#pragma unroll
            for (int c = 0; c < 12; c++) s = fmaf(sw[o * 12 + c], xv[c], s);
            g_h[n * 12 + o] = s;
        }
    } else if (b < 2160) {
        int is64 = detect_is64(ei, tid);
        int e = (b - 240) * 256 + tid;
        int src, dst;
        load_edge(ei, e, is64, src, dst);
        (void)src;
        atomicAdd(&g_deg[dst], 1.0f);
    } else if (b < 2928) {           // conv1 -> g_wC1
        int d = (b - 2160) * 256 + tid;
        int r = d / 96, rem = d - r * 96;
        int mb = r >> 8, ch = (r >> 6) & 3, o = r & 63;
        int tap = rem >> 5, cc = rem & 31;
        g_wC1[d] = __float2half(cw1[((mb * 64 + o) * 128 + ch * 32 + cc) * 3 + tap]);
    } else if (b < 3184) {           // down1 -> g_wD1
        int d = (b - 2928) * 256 + tid;
        int r = d >> 5, cc = d & 31;
        int mb = r >> 8, ch = (r >> 6) & 3, o = r & 63;
        g_wD1[d] = __float2half(dw1[(mb * 64 + o) * 128 + ch * 32 + cc]);
    } else if (b < 3952) {           // conv2 -> g_wC2
        int d = (b - 3184) * 256 + tid;
        int r = d / 96, rem = d - r * 96;
        int mb = r >> 10, ch = (r >> 6) & 15, o = r & 63;
        int tap = rem >> 5, cc = rem & 31;
        g_wC2[d] = __float2half(cw2[((mb * 64 + o) * 512 + ch * 32 + cc) * 3 + tap]);
    } else if (b < 4208) {           // down2 -> g_wD2
        int d = (b - 3952) * 256 + tid;
        int r = d >> 5, cc = d & 31;
        int mb = r >> 10, ch = (r >> 6) & 15, o = r & 63;
        g_wD2[d] = __float2half(dw2[(mb * 64 + o) * 512 + ch * 32 + cc]);
    } else {                         // fc weights -> fp16
        int idx = (b - 4208) * 256 + tid;
        if (idx < FCO * 3840) g_fcwH[idx] = __float2half(fcw[idx]);
    }
}

__global__ __launch_bounds__(256) void k_scatter(const void* ei) {
    int tid = threadIdx.x;
    int is64 = detect_is64(ei, tid);
    int e = blockIdx.x * 256 + tid;
    int src, dst;
    load_edge(ei, e, is64, src, dst);
    float norm = rsqrtf(g_deg[src] + 1.0f) * rsqrtf(g_deg[dst] + 1.0f);
    float4 h0 = *(const float4*)(g_h + src * 12);
    float4 h1 = *(const float4*)(g_h + src * 12 + 4);
    float4 h2 = *(const float4*)(g_h + src * 12 + 8);
    float* ad = &g_acc[dst * 12];
    atomicAdd(ad + 0, norm * h0.x);  atomicAdd(ad + 1, norm * h0.y);
    atomicAdd(ad + 2, norm * h0.z);  atomicAdd(ad + 3, norm * h0.w);
    atomicAdd(ad + 4, norm * h1.x);  atomicAdd(ad + 5, norm * h1.y);
    atomicAdd(ad + 6, norm * h1.z);  atomicAdd(ad + 7, norm * h1.w);
    atomicAdd(ad + 8, norm * h2.x);  atomicAdd(ad + 9, norm * h2.y);
    atomicAdd(ad + 10, norm * h2.z); atomicAdd(ad + 11, norm * h2.w);
}

// ---------------- fused gcn_out + TCN block 0 (12 -> 128, dil=1) ----------------
__global__ __launch_bounds__(128) void k_tcn0f(
    const float* __restrict__ cw, const float* __restrict__ cb,
    const float* __restrict__ dw, const float* __restrict__ db,
    const float* __restrict__ gcnb) {
    __shared__ float sx[34][12];
    int tid = threadIdx.x;
    int p0 = blockIdx.x * 32;
    for (int i = tid; i < 34 * 12; i += 128) {
        int r = i / 12, c = i % 12;
        int p = p0 - 2 + r;
        float v = 0.f;
        if (p >= 0) {
            float di = rsqrtf(g_deg[p] + 1.0f);
            v = g_acc[p * 12 + c] + di * di * g_h[p * 12 + c] + gcnb[c];
        }
        sx[r][c] = v;
    }
    __syncthreads();
    int ch = tid;
    float w[36], wd[12];
#pragma unroll
    for (int i = 0; i < 36; i++) w[i] = cw[ch * 36 + i];
#pragma unroll
    for (int i = 0; i < 12; i++) wd[i] = dw[ch * 12 + i];
    float bc = cb[ch], bd = db[ch];
    for (int j = 0; j < 32; j++) {
        int p = p0 + j;
        int t = p % 30;
        float acc = 0.f, accd = 0.f;
#pragma unroll
        for (int k = 0; k < 3; k++) {
            if (t - 2 + k >= 0) {
#pragma unroll
                for (int ci = 0; ci < 12; ci++)
                    acc = fmaf(w[ci * 3 + k], sx[j + k][ci], acc);
            }
        }
#pragma unroll
        for (int ci = 0; ci < 12; ci++) accd = fmaf(wd[ci], sx[j + 2][ci], accd);
        g_X1h[(size_t)p * 128 + ch] =
            __float2half(fmaxf(fmaxf(acc + bc, 0.f) + accd + bd, 0.f));
    }
}

// ---------------- fp16 mma TCN block: cp.async pipeline + ldmatrix ----------------
// OUTM: 1 = fp16 [pos][C]; 2 = fp16 transposed [g][c*30+t] (FC layout)
template <int CIN, int COUT, int DIL, int NCH, int OUTM>
__global__ __launch_bounds__(256, 2) void k_tcnH(
    const __half* __restrict__ Xin, const __half* __restrict__ wC,
    const __half* __restrict__ wD, const float* __restrict__ cb,
    const float* __restrict__ db, __half* __restrict__ Xout) {
    constexpr int W = 32 + 2 * DIL;
    constexpr int BBUF = 4 * W * 40;          // halves per B buffer
    constexpr int ABUF = 64 * 104;
    constexpr int DBUF = 64 * 40;
    extern __shared__ __half smh[];
    const uint32_t smem0 = (uint32_t)__cvta_generic_to_shared(smh);
    const uint32_t bSec = smem0;
    const uint32_t aSec = smem0 + 2 * BBUF * 2;
    const uint32_t dSec = aSec + 2 * ABUF * 2;

    const int tid = threadIdx.x;
    const int wrp = tid >> 5, lane = tid & 31;
    const int lr = lane >> 2, lc = lane & 3;
    const int l8 = lane & 7, s1 = (lane >> 3) & 1, s2 = lane >> 4;
    const int mh = wrp & 1;
    const int nq = wrp >> 1;
    const int mb = blockIdx.x;
    const int m0 = mb * 64;
    const int g0 = blockIdx.y * 4;

    // zero halo rows of both B buffers
    {
        constexpr int ZR = 2 * DIL + 2;
        uint4 z = make_uint4(0, 0, 0, 0);
        for (int idx = tid; idx < 2 * 4 * ZR * 5; idx += 256) {
            int bufg = idx / (ZR * 5);
            int r = idx - bufg * (ZR * 5);
            int zr = r / 5, pc = r - (r / 5) * 5;
            int u = (zr < 2 * DIL) ? zr : (30 + zr);
            int buf = bufg >> 2, gi = bufg & 3;
            *(uint4*)(smh + buf * BBUF + (gi * W + u) * 40 + pc * 8) = z;
        }
    }

    auto stage = [&](int chk, int buf) {
        uint32_t bD = bSec + buf * (BBUF * 2);
        for (int idx = tid; idx < 480; idx += 256) {
            int gi = idx / 120;
            int r = idx - gi * 120;
            int t = r >> 2, pc = r & 3;
            uint32_t dst = bD + (gi * W + t + 2 * DIL) * 80 + pc * 16;
            const __half* src = Xin + ((size_t)(g0 + gi) * 30 + t) * CIN + chk * 32 + pc * 8;
            CP16(dst, src);
        }
        uint32_t aD = aSec + buf * (ABUF * 2);
        const __half* srcA = wC + ((size_t)(mb * NCH + chk) * 64) * 96;
        for (int idx = tid; idx < 768; idx += 256) {
            int o = idx / 12, pc = idx - (idx / 12) * 12;
            CP16(aD + o * 208 + pc * 16, srcA + o * 96 + pc * 8);
        }
        uint32_t dD = dSec + buf * (DBUF * 2);
        const __half* srcD = wD + ((size_t)(mb * NCH + chk) * 64) * 32;
        {
            int o = tid >> 2, pc = tid & 3;
            CP16(dD + o * 80 + pc * 16, srcD + o * 32 + pc * 8);
        }
        CP_COMMIT();
    };

    float acc1[2][4][4], acc2[2][4][4];
#pragma unroll
    for (int mt = 0; mt < 2; mt++)
#pragma unroll
        for (int nt = 0; nt < 4; nt++)
#pragma unroll
            for (int r = 0; r < 4; r++) { acc1[mt][nt][r] = 0.f; acc2[mt][nt][r] = 0.f; }

    stage(0, 0);
    stage(1, 1);

    for (int chk = 0; chk < NCH; chk++) {
        const int buf = chk & 1;
        if (chk + 1 < NCH) { CP_WAIT1(); } else { CP_WAIT0(); }
        __syncthreads();

        const uint32_t bRow = bSec + buf * (BBUF * 2) + nq * (W * 80);
        const uint32_t aB = aSec + buf * (ABUF * 2);
        const uint32_t dB = dSec + buf * (DBUF * 2);

#pragma unroll
        for (int kh = 0; kh < 2; kh++) {
            const uint32_t kb = kh * 32;
#pragma unroll
            for (int tap = 0; tap < 3; tap++) {
                uint32_t bf[4][2];
#pragma unroll
                for (int pr = 0; pr < 2; pr++) {
                    uint32_t ba = bRow +
                        (tap * DIL + (pr * 2 + s2) * 8 + l8) * 80 + kb + s1 * 16;
                    LDMX4(bf[pr * 2][0], bf[pr * 2][1], bf[pr * 2 + 1][0], bf[pr * 2 + 1][1], ba);
                }
                uint32_t af[2][4];
#pragma unroll
                for (int mt = 0; mt < 2; mt++) {
                    uint32_t aa = aB + (mh * 32 + mt * 16 + s1 * 8 + l8) * 208 +
                                  tap * 64 + kb + s2 * 16;
                    LDMX4(af[mt][0], af[mt][1], af[mt][2], af[mt][3], aa);
                }
#pragma unroll
                for (int mt = 0; mt < 2; mt++)
#pragma unroll
                    for (int nt = 0; nt < 4; nt++)
                        mma16(acc1[mt][nt], af[mt], bf[nt]);
                if (tap == 2) {
                    uint32_t df[2][4];
#pragma unroll
                    for (int mt = 0; mt < 2; mt++) {
                        uint32_t da = dB + (mh * 32 + mt * 16 + s1 * 8 + l8) * 80 +
                                      kb + s2 * 16;
                        LDMX4(df[mt][0], df[mt][1], df[mt][2], df[mt][3], da);
                    }
#pragma unroll
                    for (int mt = 0; mt < 2; mt++)
#pragma unroll
                        for (int nt = 0; nt < 4; nt++)
                            mma16(acc2[mt][nt], df[mt], bf[nt]);
                }
            }
        }
        __syncthreads();
        if (chk + 2 < NCH) stage(chk + 2, buf);
    }

    // ---- epilogue ----
    float* sO = (float*)smh;  // [128 padded pos][68]
#pragma unroll
    for (int mt = 0; mt < 2; mt++) {
        int ob = m0 + mh * 32 + mt * 16 + lr;
        float bc0 = cb[ob], bc1 = cb[ob + 8];
        float bd0 = db[ob], bd1 = db[ob + 8];
#pragma unroll
        for (int nt = 0; nt < 4; nt++) {
#pragma unroll
            for (int r = 0; r < 4; r++) {
                float bc = (r >= 2) ? bc1 : bc0;
                float bd = (r >= 2) ? bd1 : bd0;
                int oo = mh * 32 + mt * 16 + lr + ((r >= 2) ? 8 : 0);
                int po = nq * 32 + nt * 8 + lc * 2 + (r & 1);
                float y = fmaxf(fmaxf(acc1[mt][nt][r] + bc, 0.f) + acc2[mt][nt][r] + bd, 0.f);
                sO[po * 68 + oo] = y;
            }
        }
    }
    __syncthreads();
    if (OUTM == 1) {
#pragma unroll
        for (int gi = 0; gi < 4; gi++) {
            for (int idx = tid; idx < 480; idx += 256) {
                int t = idx >> 4, q = idx & 15;
                float4 v = *(float4*)&sO[(gi * 32 + t) * 68 + q * 4];
                __half2 h0 = __floats2half2_rn(v.x, v.y);
                __half2 h1 = __floats2half2_rn(v.z, v.w);
                uint2 u;
                u.x = *(uint32_t*)&h0; u.y = *(uint32_t*)&h1;
                *(uint2*)(Xout + (size_t)((g0 + gi) * 30 + t) * COUT + m0 + q * 4) = u;
            }
        }
    } else {
        // transposed FC layout: Xout[g][ (m0+c)*30 + t ]
#pragma unroll
        for (int gi = 0; gi < 4; gi++) {
            for (int idx = tid; idx < 960; idx += 256) {
                int c = idx / 15, th = idx - (idx / 15) * 15;
                int t = th * 2;
                float a = sO[(gi * 32 + t) * 68 + c];
                float b = sO[(gi * 32 + t + 1) * 68 + c];
                __half2 h = __floats2half2_rn(a, b);
                *(__half2*)(Xout + (size_t)(g0 + gi) * 3840 + (m0 + c) * 30 + t) = h;
            }
        }
    }
}

// ---------------- tensor-core FC ----------------
// CTA = 16 graphs; 8 warps = 8 K-slices (480 k each, c-aligned). chunk=32 k,
// double-buffered cp.async. D[16g x 80j] per warp, fp32 smem reduce + bias.
#define FC_XST 40                       // halves per staged row (32 + 8 pad)
#define FC_XBUF (16 * 40)
#define FC_WBUF (80 * 40)
#define FC_STRIDE (8 * FC_XBUF + 8 * FC_WBUF)   // halves per buffer
#define FC_SMEM (2 * FC_STRIDE * 2)             // bytes

__global__ __launch_bounds__(256, 1) void k_fcM(
    const __half* __restrict__ X3T, const __half* __restrict__ fcwH,
    const float* __restrict__ fcb, float* __restrict__ out) {
    extern __shared__ __half sh[];
    const uint32_t s0 = (uint32_t)__cvta_generic_to_shared(sh);
    const int tid = threadIdx.x;
    const int wrp = tid >> 5, lane = tid & 31;
    const int l8 = lane & 7, s1 = (lane >> 3) & 1, s2 = lane >> 4;
    const int lr = lane >> 2, lc = lane & 3;
    const int g0 = blockIdx.x * 16;
    const int ks = wrp;

    auto stage = [&](int ch, int buf) {
        uint32_t base = s0 + buf * (FC_STRIDE * 2);
        for (int i = tid; i < 512; i += 256) {
            int kss = i >> 6, r = i & 63;
            int g = r >> 2, q = r & 3;
            uint32_t dst = base + (kss * FC_XBUF + g * FC_XST) * 2 + q * 16;
            const __half* src = X3T + (size_t)(g0 + g) * 3840 + kss * 480 + ch * 32 + q * 8;
            CP16(dst, src);
        }
        for (int i = tid; i < 2560; i += 256) {
            int kss = i / 320, r = i - kss * 320;
            int j = r >> 2, q = r & 3;
            uint32_t dst = base + (8 * FC_XBUF + kss * FC_WBUF + j * FC_XST) * 2 + q * 16;
            const __half* src = fcwH + (size_t)(j < FCO ? j : 0) * 3840 + kss * 480 + ch * 32 + q * 8;
            if (j < FCO) CP16(dst, src); else CP16Z(dst, src);
        }
        CP_COMMIT();
    };

    float acc[10][4];
#pragma unroll
    for (int nt = 0; nt < 10; nt++)
#pragma unroll
        for (int r = 0; r < 4; r++) acc[nt][r] = 0.f;

    stage(0, 0);
    stage(1, 1);

    for (int ch = 0; ch < 15; ch++) {
        int buf = ch & 1;
        if (ch + 1 < 15) { CP_WAIT1(); } else { CP_WAIT0(); }
        __syncthreads();
        uint32_t xB = s0 + buf * (FC_STRIDE * 2) + ks * (FC_XBUF * 2);
        uint32_t wB = s0 + buf * (FC_STRIDE * 2) + (8 * FC_XBUF + ks * FC_WBUF) * 2;
#pragma unroll
        for (int k16 = 0; k16 < 2; k16++) {
            uint32_t kb = k16 * 32;
            uint32_t af[4];
            LDMX4(af[0], af[1], af[2], af[3], xB + (s1 * 8 + l8) * 80 + kb + s2 * 16);
            uint32_t bf[10][2];
#pragma unroll
            for (int jt = 0; jt < 5; jt++) {
                LDMX4(bf[jt * 2][0], bf[jt * 2][1], bf[jt * 2 + 1][0], bf[jt * 2 + 1][1],
                      wB + (jt * 16 + s2 * 8 + l8) * 80 + kb + s1 * 16);
            }
#pragma unroll
            for (int nt = 0; nt < 10; nt++) mma16(acc[nt], af, bf[nt]);
        }
        __syncthreads();
        if (ch + 2 < 15) stage(ch + 2, buf);
    }

    // cross-warp reduce over 8 K-slices
    __syncthreads();
    float* sred = (float*)sh;   // [8][16][80]
#pragma unroll
    for (int nt = 0; nt < 10; nt++)
#pragma unroll
        for (int r = 0; r < 4; r++) {
            int g = lr + ((r & 2) ? 8 : 0);
            int j = nt * 8 + lc * 2 + (r & 1);
            sred[(ks * 16 + g) * 80 + j] = acc[nt][r];
        }
    __syncthreads();
    for (int idx = tid; idx < 16 * FCO; idx += 256) {
        int g = idx / FCO, j = idx - (idx / FCO) * FCO;
        float s = 0.f;
#pragma unroll
        for (int w2 = 0; w2 < 8; w2++) s += sred[(w2 * 16 + g) * 80 + j];
        out[(size_t)(g0 + g) * FCO + j] = s + fcb[j];
    }
}

// ---------------- launch ----------------
extern "C" void kernel_launch(void* const* d_in, const int* in_sizes, int n_in,
                              void* d_out, int out_size) {
    const float* x    = (const float*)d_in[0];
    const void*  ei   = d_in[1];
    const float* gcnw = (const float*)d_in[2];
    const float* gcnb = (const float*)d_in[3];
    const float* cw0  = (const float*)d_in[4];
    const float* cb0  = (const float*)d_in[5];
    const float* dw0  = (const float*)d_in[6];
    const float* db0  = (const float*)d_in[7];
    const float* cw1  = (const float*)d_in[8];
    const float* cb1  = (const float*)d_in[9];
    const float* dw1  = (const float*)d_in[10];
    const float* db1  = (const float*)d_in[11];
    const float* cw2  = (const float*)d_in[12];
    const float* cb2  = (const float*)d_in[13];
    const float* dw2  = (const float*)d_in[14];
    const float* db2  = (const float*)d_in[15];
    const float* fcw  = (const float*)d_in[16];
    const float* fcb  = (const float*)d_in[17];
    float* out = (float*)d_out;

    void *pX1h, *pX2h, *pX3T, *pDeg, *pAcc, *pWC1, *pWD1, *pWC2, *pWD2, *pFcwH;
    cudaGetSymbolAddress(&pX1h, g_X1h);
    cudaGetSymbolAddress(&pX2h, g_X2h);
    cudaGetSymbolAddress(&pX3T, g_X3T);
    cudaGetSymbolAddress(&pDeg, g_deg);
    cudaGetSymbolAddress(&pAcc, g_acc);
    cudaGetSymbolAddress(&pWC1, g_wC1);
    cudaGetSymbolAddress(&pWD1, g_wD1);
    cudaGetSymbolAddress(&pWC2, g_wC2);
    cudaGetSymbolAddress(&pWD2, g_wD2);
    cudaGetSymbolAddress(&pFcwH, g_fcwH);

    cudaMemsetAsync(pDeg, 0, NTOT * sizeof(float));
    cudaMemsetAsync(pAcc, 0, NTOT * 12 * sizeof(float));

    k_linDeg<<<5288, 256>>>(x, gcnw, ei, cw1, dw1, cw2, dw2, fcw);
    k_scatter<<<NE / 256, 256>>>(ei);
    k_tcn0f<<<NTOT / 32, 128>>>(cw0, cb0, dw0, db0, gcnb);

    constexpr int SM1 = (2 * 4 * 38 * 40 + 2 * 64 * 104 + 2 * 64 * 40) * 2;
    constexpr int SM2 = (2 * 4 * 50 * 40 + 2 * 64 * 104 + 2 * 64 * 40) * 2;
    cudaFuncSetAttribute((const void*)k_tcnH<128, 512, 3, 4, 1>,
                         cudaFuncAttributeMaxDynamicSharedMemorySize, SM1);
    cudaFuncSetAttribute((const void*)k_tcnH<512, 128, 9, 16, 2>,
                         cudaFuncAttributeMaxDynamicSharedMemorySize, SM2);
    k_tcnH<128, 512, 3, 4, 1><<<dim3(8, NB / 4), 256, SM1>>>(
        (const __half*)pX1h, (const __half*)pWC1, (const __half*)pWD1, cb1, db1,
        (__half*)pX2h);
    k_tcnH<512, 128, 9, 16, 2><<<dim3(2, NB / 4), 256, SM2>>>(
        (const __half*)pX2h, (const __half*)pWC2, (const __half*)pWD2, cb2, db2,
        (__half*)pX3T);

    cudaFuncSetAttribute(k_fcM, cudaFuncAttributeMaxDynamicSharedMemorySize, FC_SMEM);
    k_fcM<<<NB / 16, 256, FC_SMEM>>>((const __half*)pX3T, (const __half*)pFcwH, fcb, out);
}

// round 8
// speedup vs baseline: 9.4657x; 1.0601x over previous
#include <cuda_runtime.h>
#include <cuda_fp16.h>
#include <cstdint>

// ---------------- problem constants ----------------
#define NTOT 61440      // B*30 positions/nodes
#define NB   2048
#define NE   491520
#define FCO  72

// ---------------- scratch ----------------
__device__ float g_h[NTOT * 12];
__device__ float g_deg[NTOT];
__device__ float g_acc[NTOT * 12];
__device__ __align__(256) __half g_X1h[(size_t)NTOT * 128];
__device__ __align__(256) __half g_X2h[(size_t)NTOT * 512];
__device__ __align__(256) __half g_X3T[(size_t)NB * 3840];  // [g][c*30+t]
__device__ __align__(256) __half g_fcwH[FCO * 3840];
// pre-laid-out fp16 weights
__device__ __align__(256) __half g_wC0[2 * 64 * 48];   // [o128][tap*16+cc16] (cc>=12 zero)
__device__ __align__(256) __half g_wD0[2 * 64 * 16];
__device__ __align__(256) __half g_wC1[8 * 4 * 64 * 96];
__device__ __align__(256) __half g_wD1[8 * 4 * 64 * 32];
__device__ __align__(256) __half g_wC2[2 * 16 * 64 * 96];
__device__ __align__(256) __half g_wD2[2 * 16 * 64 * 32];

// ---------------- PTX helpers ----------------
#define CP16(d, s) asm volatile("cp.async.cg.shared.global [%0], [%1], 16;" :: "r"(d), "l"(s))
#define CP16Z(d, s) asm volatile("cp.async.cg.shared.global [%0], [%1], 16, 0;" :: "r"(d), "l"(s))
#define CP_COMMIT() asm volatile("cp.async.commit_group;" ::: "memory")
#define CP_WAIT1() asm volatile("cp.async.wait_group 1;" ::: "memory")
#define CP_WAIT0() asm volatile("cp.async.wait_group 0;" ::: "memory")
#define LDMX4(r0, r1, r2, r3, a) \
    asm volatile("ldmatrix.sync.aligned.m8n8.x4.shared.b16 {%0,%1,%2,%3}, [%4];" \
        : "=r"(r0), "=r"(r1), "=r"(r2), "=r"(r3) : "r"(a))

__device__ __forceinline__ void mma16(float* d, const uint32_t* a, const uint32_t* b) {
    asm volatile(
        "mma.sync.aligned.m16n8k16.row.col.f32.f16.f16.f32 "
        "{%0,%1,%2,%3}, {%4,%5,%6,%7}, {%8,%9}, {%0,%1,%2,%3};"
        : "+f"(d[0]), "+f"(d[1]), "+f"(d[2]), "+f"(d[3])
        : "r"(a[0]), "r"(a[1]), "r"(a[2]), "r"(a[3]), "r"(b[0]), "r"(b[1]));
}

// ---------------- edge dtype detect ----------------
__device__ __forceinline__ int detect_is64(const void* ei, int tid) {
    __shared__ int sdet;
    if (tid == 0) sdet = 0;
    __syncthreads();
    if (tid < 64) {
        int v = ((const int*)ei)[2 * tid + 1];
        if (v) atomicOr(&sdet, 1);
    }
    __syncthreads();
    return sdet == 0;
}
__device__ __forceinline__ void load_edge(const void* ei, int e, int is64, int& src, int& dst) {
    if (is64) {
        const long long* p = (const long long*)ei;
        src = (int)p[e]; dst = (int)p[NE + e];
    } else {
        const int* p = (const int*)ei;
        src = p[e]; dst = p[NE + e];
    }
}

// ---------------- mega prep kernel ----------------
__global__ __launch_bounds__(256) void k_linDeg(
    const float* __restrict__ x, const float* __restrict__ w, const void* ei,
    const float* __restrict__ cw0, const float* __restrict__ dw0,
    const float* __restrict__ cw1, const float* __restrict__ dw1,
    const float* __restrict__ cw2, const float* __restrict__ dw2,
    const float* __restrict__ fcw) {
    int tid = threadIdx.x;
    int b = blockIdx.x;
    if (b < 240) {
        __shared__ float sw[144];
        if (tid < 144) sw[tid] = w[tid];
        __syncthreads();
        int n = b * 256 + tid;
        float xv[12];
#pragma unroll
        for (int c = 0; c < 12; c++) xv[c] = x[n * 12 + c];
#pragma unroll
        for (int o = 0; o < 12; o++) {
            float s = 0.f;
#pragma unroll
            for (int c = 0; c < 12; c++) s = fmaf(sw[o * 12 + c], xv[c], s);
            g_h[n * 12 + o] = s;
        }
    } else if (b < 2160) {
        int is64 = detect_is64(ei, tid);
        int e = (b - 240) * 256 + tid;
        int src, dst;
        load_edge(ei, e, is64, src, dst);
        (void)src;
        atomicAdd(&g_deg[dst], 1.0f);
    } else if (b < 2928) {           // conv1 -> g_wC1
        int d = (b - 2160) * 256 + tid;
        int r = d / 96, rem = d - r * 96;
        int mb = r >> 8, ch = (r >> 6) & 3, o = r & 63;
        int tap = rem >> 5, cc = rem & 31;
        g_wC1[d] = __float2half(cw1[((mb * 64 + o) * 128 + ch * 32 + cc) * 3 + tap]);
    } else if (b < 3184) {           // down1 -> g_wD1
        int d = (b - 2928) * 256 + tid;
        int r = d >> 5, cc = d & 31;
        int mb = r >> 8, ch = (r >> 6) & 3, o = r & 63;
        g_wD1[d] = __float2half(dw1[(mb * 64 + o) * 128 + ch * 32 + cc]);
    } else if (b < 3952) {           // conv2 -> g_wC2
        int d = (b - 3184) * 256 + tid;
        int r = d / 96, rem = d - r * 96;
        int mb = r >> 10, ch = (r >> 6) & 15, o = r & 63;
        int tap = rem >> 5, cc = rem & 31;
        g_wC2[d] = __float2half(cw2[((mb * 64 + o) * 512 + ch * 32 + cc) * 3 + tap]);
    } else if (b < 4208) {           // down2 -> g_wD2
        int d = (b - 3952) * 256 + tid;
        int r = d >> 5, cc = d & 31;
        int mb = r >> 10, ch = (r >> 6) & 15, o = r & 63;
        g_wD2[d] = __float2half(dw2[(mb * 64 + o) * 512 + ch * 32 + cc]);
    } else if (b < 4232) {           // conv0 -> g_wC0 (K padded 12->16)
        int d = (b - 4208) * 256 + tid;
        int o2 = d / 48, rem = d - o2 * 48;
        int tap = rem >> 4, cc = rem & 15;
        g_wC0[d] = (cc < 12) ? __float2half(cw0[o2 * 36 + cc * 3 + tap])
                             : __float2half(0.f);
    } else if (b < 4240) {           // down0 -> g_wD0
        int d = (b - 4232) * 256 + tid;
        int o2 = d >> 4, cc = d & 15;
        g_wD0[d] = (cc < 12) ? __float2half(dw0[o2 * 12 + cc]) : __float2half(0.f);
    } else {                         // fc weights -> fp16
        int idx = (b - 4240) * 256 + tid;
        if (idx < FCO * 3840) g_fcwH[idx] = __float2half(fcw[idx]);
    }
}

__global__ __launch_bounds__(256) void k_scatter(const void* ei) {
    int tid = threadIdx.x;
    int is64 = detect_is64(ei, tid);
    int e = blockIdx.x * 256 + tid;
    int src, dst;
    load_edge(ei, e, is64, src, dst);
    float norm = rsqrtf(g_deg[src] + 1.0f) * rsqrtf(g_deg[dst] + 1.0f);
    float4 h0 = *(const float4*)(g_h + src * 12);
    float4 h1 = *(const float4*)(g_h + src * 12 + 4);
    float4 h2 = *(const float4*)(g_h + src * 12 + 8);
    float* ad = &g_acc[dst * 12];
    atomicAdd(ad + 0, norm * h0.x);  atomicAdd(ad + 1, norm * h0.y);
    atomicAdd(ad + 2, norm * h0.z);  atomicAdd(ad + 3, norm * h0.w);
    atomicAdd(ad + 4, norm * h1.x);  atomicAdd(ad + 5, norm * h1.y);
    atomicAdd(ad + 6, norm * h1.z);  atomicAdd(ad + 7, norm * h1.w);
    atomicAdd(ad + 8, norm * h2.x);  atomicAdd(ad + 9, norm * h2.y);
    atomicAdd(ad + 10, norm * h2.z); atomicAdd(ad + 11, norm * h2.w);
}

// ---------------- mma TCN block 0: fused gcn_out + conv(12->128,dil=1) ----------------
// CTA = 64 out-ch x 4 graphs. B [gi][u(34)][16+8pad] stride 48B; A [o][tap*16+cc]
// stride 112B; D [o][16+8pad] stride 48B. Single chunk (K=16), 32 mma/warp.
#define SM0_BYTES (128 * 68 * 4)     // epilogue dominates (34816 B)

__global__ __launch_bounds__(256, 2) void k_tcn0M(
    const __half* __restrict__ wC, const __half* __restrict__ wD,
    const float* __restrict__ cb, const float* __restrict__ db,
    const float* __restrict__ gcnb) {
    extern __shared__ __half sh0[];
    const uint32_t s0 = (uint32_t)__cvta_generic_to_shared(sh0);
    __half* sB = sh0;                 // 4*34*24 = 3264 halves
    const uint32_t aOff = 3264 * 2;   // sA: 64*56 halves
    const uint32_t dOff = (3264 + 3584) * 2;  // sD: 64*24 halves

    const int tid = threadIdx.x;
    const int wrp = tid >> 5, lane = tid & 31;
    const int lr = lane >> 2, lc = lane & 3;
    const int l8 = lane & 7, s1 = (lane >> 3) & 1, s2 = lane >> 4;
    const int mh = wrp & 1;
    const int nq = wrp >> 1;
    const int mb = blockIdx.x;
    const int m0 = mb * 64;
    const int g0 = blockIdx.y * 4;

    // A/D weights via cp.async
    for (int idx = tid; idx < 384; idx += 256) {
        int o = idx / 6, pc = idx - (idx / 6) * 6;
        CP16(s0 + aOff + o * 112 + pc * 16, wC + (size_t)(mb * 64 + o) * 48 + pc * 8);
    }
    if (tid < 128) {
        int o = tid >> 1, pc = tid & 1;
        CP16(s0 + dOff + o * 48 + pc * 16, wD + (size_t)(mb * 64 + o) * 16 + pc * 8);
    }
    CP_COMMIT();

    // zero B tile, then fill with gcn_out values
    {
        uint4 z = make_uint4(0, 0, 0, 0);
        for (int idx = tid; idx < 408; idx += 256) ((uint4*)sB)[idx] = z;
    }
    __syncthreads();
    for (int idx = tid; idx < 1440; idx += 256) {
        int gi = idx / 360;
        int r = idx - gi * 360;
        int t = r / 12, c = r - (r / 12) * 12;
        int p = (g0 + gi) * 30 + t;
        float di2 = 1.0f / (g_deg[p] + 1.0f);
        float v = g_acc[p * 12 + c] + di2 * g_h[p * 12 + c] + gcnb[c];
        sB[(gi * 34 + t + 2) * 24 + c] = __float2half(v);
    }
    CP_WAIT0();
    __syncthreads();

    float acc1[2][4][4], acc2[2][4][4];
#pragma unroll
    for (int mt = 0; mt < 2; mt++)
#pragma unroll
        for (int nt = 0; nt < 4; nt++)
#pragma unroll
            for (int r = 0; r < 4; r++) { acc1[mt][nt][r] = 0.f; acc2[mt][nt][r] = 0.f; }

    const uint32_t bRow = s0 + nq * (34 * 48);
#pragma unroll
    for (int tap = 0; tap < 3; tap++) {
        uint32_t bf[4][2];
#pragma unroll
        for (int pr = 0; pr < 2; pr++) {
            uint32_t ba = bRow + (tap + (pr * 2 + s2) * 8 + l8) * 48 + s1 * 16;
            LDMX4(bf[pr * 2][0], bf[pr * 2][1], bf[pr * 2 + 1][0], bf[pr * 2 + 1][1], ba);
        }
        uint32_t af[2][4];
#pragma unroll
        for (int mt = 0; mt < 2; mt++) {
            uint32_t aa = s0 + aOff + (mh * 32 + mt * 16 + s1 * 8 + l8) * 112 +
                          tap * 32 + s2 * 16;
            LDMX4(af[mt][0], af[mt][1], af[mt][2], af[mt][3], aa);
        }
#pragma unroll
        for (int mt = 0; mt < 2; mt++)
#pragma unroll
            for (int nt = 0; nt < 4; nt++)
                mma16(acc1[mt][nt], af[mt], bf[nt]);
        if (tap == 2) {
            uint32_t df[2][4];
#pragma unroll
            for (int mt = 0; mt < 2; mt++) {
                uint32_t da = s0 + dOff + (mh * 32 + mt * 16 + s1 * 8 + l8) * 48 + s2 * 16;
                LDMX4(df[mt][0], df[mt][1], df[mt][2], df[mt][3], da);
            }
#pragma unroll
            for (int mt = 0; mt < 2; mt++)
#pragma unroll
                for (int nt = 0; nt < 4; nt++)
                    mma16(acc2[mt][nt], df[mt], bf[nt]);
        }
    }
    __syncthreads();

    // epilogue -> g_X1h [pos][128]
    float* sO = (float*)sh0;  // [128 padded pos][68]
#pragma unroll
    for (int mt = 0; mt < 2; mt++) {
        int ob = m0 + mh * 32 + mt * 16 + lr;
        float bc0 = cb[ob], bc1 = cb[ob + 8];
        float bd0 = db[ob], bd1 = db[ob + 8];
#pragma unroll
        for (int nt = 0; nt < 4; nt++) {
#pragma unroll
            for (int r = 0; r < 4; r++) {
                float bc = (r >= 2) ? bc1 : bc0;
                float bd = (r >= 2) ? bd1 : bd0;
                int oo = mh * 32 + mt * 16 + lr + ((r >= 2) ? 8 : 0);
                int po = nq * 32 + nt * 8 + lc * 2 + (r & 1);
                float y = fmaxf(fmaxf(acc1[mt][nt][r] + bc, 0.f) + acc2[mt][nt][r] + bd, 0.f);
                sO[po * 68 + oo] = y;
            }
        }
    }
    __syncthreads();
#pragma unroll
    for (int gi = 0; gi < 4; gi++) {
        for (int idx = tid; idx < 480; idx += 256) {
            int t = idx >> 4, q = idx & 15;
            float4 v = *(float4*)&sO[(gi * 32 + t) * 68 + q * 4];
            __half2 h0 = __floats2half2_rn(v.x, v.y);
            __half2 h1 = __floats2half2_rn(v.z, v.w);
            uint2 u;
            u.x = *(uint32_t*)&h0; u.y = *(uint32_t*)&h1;
            *(uint2*)(g_X1h + (size_t)((g0 + gi) * 30 + t) * 128 + m0 + q * 4) = u;
        }
    }
}

// ---------------- fp16 mma TCN block: cp.async pipeline + ldmatrix ----------------
// OUTM: 1 = fp16 [pos][C]; 2 = fp16 transposed [g][c*30+t] (FC layout)
template <int CIN, int COUT, int DIL, int NCH, int OUTM>
__global__ __launch_bounds__(256, 2) void k_tcnH(
    const __half* __restrict__ Xin, const __half* __restrict__ wC,
    const __half* __restrict__ wD, const float* __restrict__ cb,
    const float* __restrict__ db, __half* __restrict__ Xout) {
    constexpr int W = 32 + 2 * DIL;
    constexpr int BBUF = 4 * W * 40;
    constexpr int ABUF = 64 * 104;
    constexpr int DBUF = 64 * 40;
    extern __shared__ __half smh[];
    const uint32_t smem0 = (uint32_t)__cvta_generic_to_shared(smh);
    const uint32_t bSec = smem0;
    const uint32_t aSec = smem0 + 2 * BBUF * 2;
    const uint32_t dSec = aSec + 2 * ABUF * 2;

    const int tid = threadIdx.x;
    const int wrp = tid >> 5, lane = tid & 31;
    const int lr = lane >> 2, lc = lane & 3;
    const int l8 = lane & 7, s1 = (lane >> 3) & 1, s2 = lane >> 4;
    const int mh = wrp & 1;
    const int nq = wrp >> 1;
    const int mb = blockIdx.x;
    const int m0 = mb * 64;
    const int g0 = blockIdx.y * 4;

    {
        constexpr int ZR = 2 * DIL + 2;
        uint4 z = make_uint4(0, 0, 0, 0);
        for (int idx = tid; idx < 2 * 4 * ZR * 5; idx += 256) {
            int bufg = idx / (ZR * 5);
            int r = idx - bufg * (ZR * 5);
            int zr = r / 5, pc = r - (r / 5) * 5;
            int u = (zr < 2 * DIL) ? zr : (30 + zr);
            int buf = bufg >> 2, gi = bufg & 3;
            *(uint4*)(smh + buf * BBUF + (gi * W + u) * 40 + pc * 8) = z;
        }
    }

    auto stage = [&](int chk, int buf) {
        uint32_t bD = bSec + buf * (BBUF * 2);
        for (int idx = tid; idx < 480; idx += 256) {
            int gi = idx / 120;
            int r = idx - gi * 120;
            int t = r >> 2, pc = r & 3;
            uint32_t dst = bD + (gi * W + t + 2 * DIL) * 80 + pc * 16;
            const __half* src = Xin + ((size_t)(g0 + gi) * 30 + t) * CIN + chk * 32 + pc * 8;
            CP16(dst, src);
        }
        uint32_t aD = aSec + buf * (ABUF * 2);
        const __half* srcA = wC + ((size_t)(mb * NCH + chk) * 64) * 96;
        for (int idx = tid; idx < 768; idx += 256) {
            int o = idx / 12, pc = idx - (idx / 12) * 12;
            CP16(aD + o * 208 + pc * 16, srcA + o * 96 + pc * 8);
        }
        uint32_t dD = dSec + buf * (DBUF * 2);
        const __half* srcD = wD + ((size_t)(mb * NCH + chk) * 64) * 32;
        {
            int o = tid >> 2, pc = tid & 3;
            CP16(dD + o * 80 + pc * 16, srcD + o * 32 + pc * 8);
        }
        CP_COMMIT();
    };

    float acc1[2][4][4], acc2[2][4][4];
#pragma unroll
    for (int mt = 0; mt < 2; mt++)
#pragma unroll
        for (int nt = 0; nt < 4; nt++)
#pragma unroll
            for (int r = 0; r < 4; r++) { acc1[mt][nt][r] = 0.f; acc2[mt][nt][r] = 0.f; }

    stage(0, 0);
    stage(1, 1);

    for (int chk = 0; chk < NCH; chk++) {
        const int buf = chk & 1;
        if (chk + 1 < NCH) { CP_WAIT1(); } else { CP_WAIT0(); }
        __syncthreads();

        const uint32_t bRow = bSec + buf * (BBUF * 2) + nq * (W * 80);
        const uint32_t aB = aSec + buf * (ABUF * 2);
        const uint32_t dB = dSec + buf * (DBUF * 2);

#pragma unroll
        for (int kh = 0; kh < 2; kh++) {
            const uint32_t kb = kh * 32;
#pragma unroll
            for (int tap = 0; tap < 3; tap++) {
                uint32_t bf[4][2];
#pragma unroll
                for (int pr = 0; pr < 2; pr++) {
                    uint32_t ba = bRow +
                        (tap * DIL + (pr * 2 + s2) * 8 + l8) * 80 + kb + s1 * 16;
                    LDMX4(bf[pr * 2][0], bf[pr * 2][1], bf[pr * 2 + 1][0], bf[pr * 2 + 1][1], ba);
                }
                uint32_t af[2][4];
#pragma unroll
                for (int mt = 0; mt < 2; mt++) {
                    uint32_t aa = aB + (mh * 32 + mt * 16 + s1 * 8 + l8) * 208 +
                                  tap * 64 + kb + s2 * 16;
                    LDMX4(af[mt][0], af[mt][1], af[mt][2], af[mt][3], aa);
                }
#pragma unroll
                for (int mt = 0; mt < 2; mt++)
#pragma unroll
                    for (int nt = 0; nt < 4; nt++)
                        mma16(acc1[mt][nt], af[mt], bf[nt]);
                if (tap == 2) {
                    uint32_t df[2][4];
#pragma unroll
                    for (int mt = 0; mt < 2; mt++) {
                        uint32_t da = dB + (mh * 32 + mt * 16 + s1 * 8 + l8) * 80 +
                                      kb + s2 * 16;
                        LDMX4(df[mt][0], df[mt][1], df[mt][2], df[mt][3], da);
                    }
#pragma unroll
                    for (int mt = 0; mt < 2; mt++)
#pragma unroll
                        for (int nt = 0; nt < 4; nt++)
                            mma16(acc2[mt][nt], df[mt], bf[nt]);
                }
            }
        }
        __syncthreads();
        if (chk + 2 < NCH) stage(chk + 2, buf);
    }

    float* sO = (float*)smh;
#pragma unroll
    for (int mt = 0; mt < 2; mt++) {
        int ob = m0 + mh * 32 + mt * 16 + lr;
        float bc0 = cb[ob], bc1 = cb[ob + 8];
        float bd0 = db[ob], bd1 = db[ob + 8];
#pragma unroll
        for (int nt = 0; nt < 4; nt++) {
#pragma unroll
            for (int r = 0; r < 4; r++) {
                float bc = (r >= 2) ? bc1 : bc0;
                float bd = (r >= 2) ? bd1 : bd0;
                int oo = mh * 32 + mt * 16 + lr + ((r >= 2) ? 8 : 0);
                int po = nq * 32 + nt * 8 + lc * 2 + (r & 1);
                float y = fmaxf(fmaxf(acc1[mt][nt][r] + bc, 0.f) + acc2[mt][nt][r] + bd, 0.f);
                sO[po * 68 + oo] = y;
            }
        }
    }
    __syncthreads();
    if (OUTM == 1) {
#pragma unroll
        for (int gi = 0; gi < 4; gi++) {
            for (int idx = tid; idx < 480; idx += 256) {
                int t = idx >> 4, q = idx & 15;
                float4 v = *(float4*)&sO[(gi * 32 + t) * 68 + q * 4];
                __half2 h0 = __floats2half2_rn(v.x, v.y);
                __half2 h1 = __floats2half2_rn(v.z, v.w);
                uint2 u;
                u.x = *(uint32_t*)&h0; u.y = *(uint32_t*)&h1;
                *(uint2*)(Xout + (size_t)((g0 + gi) * 30 + t) * COUT + m0 + q * 4) = u;
            }
        }
    } else {
#pragma unroll
        for (int gi = 0; gi < 4; gi++) {
            for (int idx = tid; idx < 960; idx += 256) {
                int c = idx / 15, th = idx - (idx / 15) * 15;
                int t = th * 2;
                float a = sO[(gi * 32 + t) * 68 + c];
                float b = sO[(gi * 32 + t + 1) * 68 + c];
                __half2 h = __floats2half2_rn(a, b);
                *(__half2*)(Xout + (size_t)(g0 + gi) * 3840 + (m0 + c) * 30 + t) = h;
            }
        }
    }
}

// ---------------- tensor-core FC ----------------
#define FC_XST 40
#define FC_XBUF (16 * 40)
#define FC_WBUF (80 * 40)
#define FC_STRIDE (8 * FC_XBUF + 8 * FC_WBUF)
#define FC_SMEM (2 * FC_STRIDE * 2)

__global__ __launch_bounds__(256, 1) void k_fcM(
    const __half* __restrict__ X3T, const __half* __restrict__ fcwH,
    const float* __restrict__ fcb, float* __restrict__ out) {
    extern __shared__ __half sh[];
    const uint32_t s0 = (uint32_t)__cvta_generic_to_shared(sh);
    const int tid = threadIdx.x;
    const int wrp = tid >> 5, lane = tid & 31;
    const int l8 = lane & 7, s1 = (lane >> 3) & 1, s2 = lane >> 4;
    const int lr = lane >> 2, lc = lane & 3;
    const int g0 = blockIdx.x * 16;
    const int ks = wrp;

    auto stage = [&](int ch, int buf) {
        uint32_t base = s0 + buf * (FC_STRIDE * 2);
        for (int i = tid; i < 512; i += 256) {
            int kss = i >> 6, r = i & 63;
            int g = r >> 2, q = r & 3;
            uint32_t dst = base + (kss * FC_XBUF + g * FC_XST) * 2 + q * 16;
            const __half* src = X3T + (size_t)(g0 + g) * 3840 + kss * 480 + ch * 32 + q * 8;
            CP16(dst, src);
        }
        for (int i = tid; i < 2560; i += 256) {
            int kss = i / 320, r = i - kss * 320;
            int j = r >> 2, q = r & 3;
            uint32_t dst = base + (8 * FC_XBUF + kss * FC_WBUF + j * FC_XST) * 2 + q * 16;
            const __half* src = fcwH + (size_t)(j < FCO ? j : 0) * 3840 + kss * 480 + ch * 32 + q * 8;
            if (j < FCO) CP16(dst, src); else CP16Z(dst, src);
        }
        CP_COMMIT();
    };

    float acc[10][4];
#pragma unroll
    for (int nt = 0; nt < 10; nt++)
#pragma unroll
        for (int r = 0; r < 4; r++) acc[nt][r] = 0.f;

    stage(0, 0);
    stage(1, 1);

    for (int ch = 0; ch < 15; ch++) {
        int buf = ch & 1;
        if (ch + 1 < 15) { CP_WAIT1(); } else { CP_WAIT0(); }
        __syncthreads();
        uint32_t xB = s0 + buf * (FC_STRIDE * 2) + ks * (FC_XBUF * 2);
        uint32_t wB = s0 + buf * (FC_STRIDE * 2) + (8 * FC_XBUF + ks * FC_WBUF) * 2;
#pragma unroll
        for (int k16 = 0; k16 < 2; k16++) {
            uint32_t kb = k16 * 32;
            uint32_t af[4];
            LDMX4(af[0], af[1], af[2], af[3], xB + (s1 * 8 + l8) * 80 + kb + s2 * 16);
            uint32_t bf[10][2];
#pragma unroll
            for (int jt = 0; jt < 5; jt++) {
                LDMX4(bf[jt * 2][0], bf[jt * 2][1], bf[jt * 2 + 1][0], bf[jt * 2 + 1][1],
                      wB + (jt * 16 + s2 * 8 + l8) * 80 + kb + s1 * 16);
            }
#pragma unroll
            for (int nt = 0; nt < 10; nt++) mma16(acc[nt], af, bf[nt]);
        }
        __syncthreads();
        if (ch + 2 < 15) stage(ch + 2, buf);
    }

    __syncthreads();
    float* sred = (float*)sh;
#pragma unroll
    for (int nt = 0; nt < 10; nt++)
#pragma unroll
        for (int r = 0; r < 4; r++) {
            int g = lr + ((r & 2) ? 8 : 0);
            int j = nt * 8 + lc * 2 + (r & 1);
            sred[(ks * 16 + g) * 80 + j] = acc[nt][r];
        }
    __syncthreads();
    for (int idx = tid; idx < 16 * FCO; idx += 256) {
        int g = idx / FCO, j = idx - (idx / FCO) * FCO;
        float s = 0.f;
#pragma unroll
        for (int w2 = 0; w2 < 8; w2++) s += sred[(w2 * 16 + g) * 80 + j];
        out[(size_t)(g0 + g) * FCO + j] = s + fcb[j];
    }
}

// ---------------- launch ----------------
extern "C" void kernel_launch(void* const* d_in, const int* in_sizes, int n_in,
                              void* d_out, int out_size) {
    const float* x    = (const float*)d_in[0];
    const void*  ei   = d_in[1];
    const float* gcnw = (const float*)d_in[2];
    const float* gcnb = (const float*)d_in[3];
    const float* cw0  = (const float*)d_in[4];
    const float* cb0  = (const float*)d_in[5];
    const float* dw0  = (const float*)d_in[6];
    const float* db0  = (const float*)d_in[7];
    const float* cw1  = (const float*)d_in[8];
    const float* cb1  = (const float*)d_in[9];
    const float* dw1  = (const float*)d_in[10];
    const float* db1  = (const float*)d_in[11];
    const float* cw2  = (const float*)d_in[12];
    const float* cb2  = (const float*)d_in[13];
    const float* dw2  = (const float*)d_in[14];
    const float* db2  = (const float*)d_in[15];
    const float* fcw  = (const float*)d_in[16];
    const float* fcb  = (const float*)d_in[17];
    float* out = (float*)d_out;

    void *pX1h, *pX2h, *pX3T, *pDeg, *pAcc;
    void *pWC0, *pWD0, *pWC1, *pWD1, *pWC2, *pWD2, *pFcwH;
    cudaGetSymbolAddress(&pX1h, g_X1h);
    cudaGetSymbolAddress(&pX2h, g_X2h);
    cudaGetSymbolAddress(&pX3T, g_X3T);
    cudaGetSymbolAddress(&pDeg, g_deg);
    cudaGetSymbolAddress(&pAcc, g_acc);
    cudaGetSymbolAddress(&pWC0, g_wC0);
    cudaGetSymbolAddress(&pWD0, g_wD0);
    cudaGetSymbolAddress(&pWC1, g_wC1);
    cudaGetSymbolAddress(&pWD1, g_wD1);
    cudaGetSymbolAddress(&pWC2, g_wC2);
    cudaGetSymbolAddress(&pWD2, g_wD2);
    cudaGetSymbolAddress(&pFcwH, g_fcwH);

    cudaMemsetAsync(pDeg, 0, NTOT * sizeof(float));
    cudaMemsetAsync(pAcc, 0, NTOT * 12 * sizeof(float));

    k_linDeg<<<5320, 256>>>(x, gcnw, ei, cw0, dw0, cw1, dw1, cw2, dw2, fcw);
    k_scatter<<<NE / 256, 256>>>(ei);

    cudaFuncSetAttribute(k_tcn0M, cudaFuncAttributeMaxDynamicSharedMemorySize, SM0_BYTES);
    k_tcn0M<<<dim3(2, NB / 4), 256, SM0_BYTES>>>(
        (const __half*)pWC0, (const __half*)pWD0, cb0, db0, gcnb);

    constexpr int SM1 = (2 * 4 * 38 * 40 + 2 * 64 * 104 + 2 * 64 * 40) * 2;
    constexpr int SM2 = (2 * 4 * 50 * 40 + 2 * 64 * 104 + 2 * 64 * 40) * 2;
    cudaFuncSetAttribute((const void*)k_tcnH<128, 512, 3, 4, 1>,
                         cudaFuncAttributeMaxDynamicSharedMemorySize, SM1);
    cudaFuncSetAttribute((const void*)k_tcnH<512, 128, 9, 16, 2>,
                         cudaFuncAttributeMaxDynamicSharedMemorySize, SM2);
    k_tcnH<128, 512, 3, 4, 1><<<dim3(8, NB / 4), 256, SM1>>>(
        (const __half*)pX1h, (const __half*)pWC1, (const __half*)pWD1, cb1, db1,
        (__half*)pX2h);
    k_tcnH<512, 128, 9, 16, 2><<<dim3(2, NB / 4), 256, SM2>>>(
        (const __half*)pX2h, (const __half*)pWC2, (const __half*)pWD2, cb2, db2,
        (__half*)pX3T);

    cudaFuncSetAttribute(k_fcM, cudaFuncAttributeMaxDynamicSharedMemorySize, FC_SMEM);
    k_fcM<<<NB / 16, 256, FC_SMEM>>>((const __half*)pX3T, (const __half*)pFcwH, fcb, out);
}

// round 9
// speedup vs baseline: 10.2206x; 1.0797x over previous
#include <cuda_runtime.h>
#include <cuda_fp16.h>
#include <cstdint>

// ---------------- problem constants ----------------
#define NTOT 61440      // B*30 positions/nodes
#define NB   2048
#define NE   491520
#define FCO  72

// ---------------- scratch ----------------
__device__ float g_h[NTOT * 12];
__device__ float g_deg[NTOT];
__device__ __align__(256) float g_acc[NTOT * 12];
__device__ __align__(256) __half g_X1h[(size_t)NTOT * 128];
__device__ __align__(256) __half g_X2h[(size_t)NTOT * 512];
__device__ __align__(256) __half g_X3T[(size_t)NB * 3840];  // [g][c*30+t]
__device__ __align__(256) __half g_fcwH[FCO * 3840];
// pre-laid-out fp16 weights
__device__ __align__(256) __half g_wC0[2 * 64 * 48];
__device__ __align__(256) __half g_wD0[2 * 64 * 16];
__device__ __align__(256) __half g_wC1[8 * 4 * 64 * 96];
__device__ __align__(256) __half g_wD1[8 * 4 * 64 * 32];
__device__ __align__(256) __half g_wC2[2 * 16 * 64 * 96];
__device__ __align__(256) __half g_wD2[2 * 16 * 64 * 32];

// ---------------- PTX helpers ----------------
#define CP16(d, s) asm volatile("cp.async.cg.shared.global [%0], [%1], 16;" :: "r"(d), "l"(s))
#define CP16Z(d, s) asm volatile("cp.async.cg.shared.global [%0], [%1], 16, 0;" :: "r"(d), "l"(s))
#define CP_COMMIT() asm volatile("cp.async.commit_group;" ::: "memory")
#define CP_WAIT1() asm volatile("cp.async.wait_group 1;" ::: "memory")
#define CP_WAIT0() asm volatile("cp.async.wait_group 0;" ::: "memory")
#define LDMX4(r0, r1, r2, r3, a) \
    asm volatile("ldmatrix.sync.aligned.m8n8.x4.shared.b16 {%0,%1,%2,%3}, [%4];" \
        : "=r"(r0), "=r"(r1), "=r"(r2), "=r"(r3) : "r"(a))

__device__ __forceinline__ void mma16(float* d, const uint32_t* a, const uint32_t* b) {
    asm volatile(
        "mma.sync.aligned.m16n8k16.row.col.f32.f16.f16.f32 "
        "{%0,%1,%2,%3}, {%4,%5,%6,%7}, {%8,%9}, {%0,%1,%2,%3};"
        : "+f"(d[0]), "+f"(d[1]), "+f"(d[2]), "+f"(d[3])
        : "r"(a[0]), "r"(a[1]), "r"(a[2]), "r"(a[3]), "r"(b[0]), "r"(b[1]));
}
__device__ __forceinline__ void red4(float* addr, float a, float b, float c, float d) {
    asm volatile("red.global.add.v4.f32 [%0], {%1,%2,%3,%4};"
                 :: "l"(addr), "f"(a), "f"(b), "f"(c), "f"(d) : "memory");
}

// ---------------- edge dtype detect ----------------
__device__ __forceinline__ int detect_is64(const void* ei, int tid) {
    __shared__ int sdet;
    if (tid == 0) sdet = 0;
    __syncthreads();
    if (tid < 64) {
        int v = ((const int*)ei)[2 * tid + 1];
        if (v) atomicOr(&sdet, 1);
    }
    __syncthreads();
    return sdet == 0;
}
__device__ __forceinline__ void load_edge(const void* ei, int e, int is64, int& src, int& dst) {
    if (is64) {
        const long long* p = (const long long*)ei;
        src = (int)p[e]; dst = (int)p[NE + e];
    } else {
        const int* p = (const int*)ei;
        src = p[e]; dst = p[NE + e];
    }
}

// ---------------- mega prep kernel ----------------
__global__ __launch_bounds__(256) void k_linDeg(
    const float* __restrict__ x, const float* __restrict__ w, const void* ei,
    const float* __restrict__ cw0, const float* __restrict__ dw0,
    const float* __restrict__ cw1, const float* __restrict__ dw1,
    const float* __restrict__ cw2, const float* __restrict__ dw2,
    const float* __restrict__ fcw) {
    int tid = threadIdx.x;
    int b = blockIdx.x;
    if (b < 240) {
        __shared__ float sw[144];
        if (tid < 144) sw[tid] = w[tid];
        __syncthreads();
        int n = b * 256 + tid;
        float xv[12];
#pragma unroll
        for (int c = 0; c < 12; c++) xv[c] = x[n * 12 + c];
#pragma unroll
        for (int o = 0; o < 12; o++) {
            float s = 0.f;
#pragma unroll
            for (int c = 0; c < 12; c++) s = fmaf(sw[o * 12 + c], xv[c], s);
            g_h[n * 12 + o] = s;
        }
    } else if (b < 2160) {
        int is64 = detect_is64(ei, tid);
        int e = (b - 240) * 256 + tid;
        int src, dst;
        load_edge(ei, e, is64, src, dst);
        (void)src;
        atomicAdd(&g_deg[dst], 1.0f);
    } else if (b < 2928) {           // conv1 -> g_wC1
        int d = (b - 2160) * 256 + tid;
        int r = d / 96, rem = d - r * 96;
        int mb = r >> 8, ch = (r >> 6) & 3, o = r & 63;
        int tap = rem >> 5, cc = rem & 31;
        g_wC1[d] = __float2half(cw1[((mb * 64 + o) * 128 + ch * 32 + cc) * 3 + tap]);
    } else if (b < 3184) {           // down1 -> g_wD1
        int d = (b - 2928) * 256 + tid;
        int r = d >> 5, cc = d & 31;
        int mb = r >> 8, ch = (r >> 6) & 3, o = r & 63;
        g_wD1[d] = __float2half(dw1[(mb * 64 + o) * 128 + ch * 32 + cc]);
    } else if (b < 3952) {           // conv2 -> g_wC2
        int d = (b - 3184) * 256 + tid;
        int r = d / 96, rem = d - r * 96;
        int mb = r >> 10, ch = (r >> 6) & 15, o = r & 63;
        int tap = rem >> 5, cc = rem & 31;
        g_wC2[d] = __float2half(cw2[((mb * 64 + o) * 512 + ch * 32 + cc) * 3 + tap]);
    } else if (b < 4208) {           // down2 -> g_wD2
        int d = (b - 3952) * 256 + tid;
        int r = d >> 5, cc = d & 31;
        int mb = r >> 10, ch = (r >> 6) & 15, o = r & 63;
        g_wD2[d] = __float2half(dw2[(mb * 64 + o) * 512 + ch * 32 + cc]);
    } else if (b < 4232) {           // conv0 -> g_wC0 (K padded 12->16)
        int d = (b - 4208) * 256 + tid;
        int o2 = d / 48, rem = d - o2 * 48;
        int tap = rem >> 4, cc = rem & 15;
        g_wC0[d] = (cc < 12) ? __float2half(cw0[o2 * 36 + cc * 3 + tap])
                             : __float2half(0.f);
    } else if (b < 4240) {           // down0 -> g_wD0
        int d = (b - 4232) * 256 + tid;
        int o2 = d >> 4, cc = d & 15;
        g_wD0[d] = (cc < 12) ? __float2half(dw0[o2 * 12 + cc]) : __float2half(0.f);
    } else {                         // fc weights -> fp16
        int idx = (b - 4240) * 256 + tid;
        if (idx < FCO * 3840) g_fcwH[idx] = __float2half(fcw[idx]);
    }
}

__global__ __launch_bounds__(256) void k_scatter(const void* ei) {
    int tid = threadIdx.x;
    int is64 = detect_is64(ei, tid);
    int e = blockIdx.x * 256 + tid;
    int src, dst;
    load_edge(ei, e, is64, src, dst);
    float norm = rsqrtf(g_deg[src] + 1.0f) * rsqrtf(g_deg[dst] + 1.0f);
    float4 h0 = *(const float4*)(g_h + src * 12);
    float4 h1 = *(const float4*)(g_h + src * 12 + 4);
    float4 h2 = *(const float4*)(g_h + src * 12 + 8);
    float* ad = &g_acc[dst * 12];
    red4(ad,     norm * h0.x, norm * h0.y, norm * h0.z, norm * h0.w);
    red4(ad + 4, norm * h1.x, norm * h1.y, norm * h1.z, norm * h1.w);
    red4(ad + 8, norm * h2.x, norm * h2.y, norm * h2.z, norm * h2.w);
}

// ---------------- mma TCN block 0: fused gcn_out + conv(12->128,dil=1) ----------------
#define SM0_BYTES (128 * 68 * 4)

__global__ __launch_bounds__(256, 2) void k_tcn0M(
    const __half* __restrict__ wC, const __half* __restrict__ wD,
    const float* __restrict__ cb, const float* __restrict__ db,
    const float* __restrict__ gcnb) {
    extern __shared__ __half sh0[];
    const uint32_t s0 = (uint32_t)__cvta_generic_to_shared(sh0);
    __half* sB = sh0;
    const uint32_t aOff = 3264 * 2;
    const uint32_t dOff = (3264 + 3584) * 2;

    const int tid = threadIdx.x;
    const int wrp = tid >> 5, lane = tid & 31;
    const int lr = lane >> 2, lc = lane & 3;
    const int l8 = lane & 7, s1 = (lane >> 3) & 1, s2 = lane >> 4;
    const int mh = wrp & 1;
    const int nq = wrp >> 1;
    const int mb = blockIdx.x;
    const int m0 = mb * 64;
    const int g0 = blockIdx.y * 4;

    for (int idx = tid; idx < 384; idx += 256) {
        int o = idx / 6, pc = idx - (idx / 6) * 6;
        CP16(s0 + aOff + o * 112 + pc * 16, wC + (size_t)(mb * 64 + o) * 48 + pc * 8);
    }
    if (tid < 128) {
        int o = tid >> 1, pc = tid & 1;
        CP16(s0 + dOff + o * 48 + pc * 16, wD + (size_t)(mb * 64 + o) * 16 + pc * 8);
    }
    CP_COMMIT();

    {
        uint4 z = make_uint4(0, 0, 0, 0);
        for (int idx = tid; idx < 408; idx += 256) ((uint4*)sB)[idx] = z;
    }
    __syncthreads();
    for (int idx = tid; idx < 1440; idx += 256) {
        int gi = idx / 360;
        int r = idx - gi * 360;
        int t = r / 12, c = r - (r / 12) * 12;
        int p = (g0 + gi) * 30 + t;
        float di2 = 1.0f / (g_deg[p] + 1.0f);
        float v = g_acc[p * 12 + c] + di2 * g_h[p * 12 + c] + gcnb[c];
        sB[(gi * 34 + t + 2) * 24 + c] = __float2half(v);
    }
    CP_WAIT0();
    __syncthreads();

    float acc1[2][4][4], acc2[2][4][4];
#pragma unroll
    for (int mt = 0; mt < 2; mt++)
#pragma unroll
        for (int nt = 0; nt < 4; nt++)
#pragma unroll
            for (int r = 0; r < 4; r++) { acc1[mt][nt][r] = 0.f; acc2[mt][nt][r] = 0.f; }

    const uint32_t bRow = s0 + nq * (34 * 48);
#pragma unroll
    for (int tap = 0; tap < 3; tap++) {
        uint32_t bf[4][2];
#pragma unroll
        for (int pr = 0; pr < 2; pr++) {
            uint32_t ba = bRow + (tap + (pr * 2 + s2) * 8 + l8) * 48 + s1 * 16;
            LDMX4(bf[pr * 2][0], bf[pr * 2][1], bf[pr * 2 + 1][0], bf[pr * 2 + 1][1], ba);
        }
        uint32_t af[2][4];
#pragma unroll
        for (int mt = 0; mt < 2; mt++) {
            uint32_t aa = s0 + aOff + (mh * 32 + mt * 16 + s1 * 8 + l8) * 112 +
                          tap * 32 + s2 * 16;
            LDMX4(af[mt][0], af[mt][1], af[mt][2], af[mt][3], aa);
        }
#pragma unroll
        for (int mt = 0; mt < 2; mt++)
#pragma unroll
            for (int nt = 0; nt < 4; nt++)
                mma16(acc1[mt][nt], af[mt], bf[nt]);
        if (tap == 2) {
            uint32_t df[2][4];
#pragma unroll
            for (int mt = 0; mt < 2; mt++) {
                uint32_t da = s0 + dOff + (mh * 32 + mt * 16 + s1 * 8 + l8) * 48 + s2 * 16;
                LDMX4(df[mt][0], df[mt][1], df[mt][2], df[mt][3], da);
            }
#pragma unroll
            for (int mt = 0; mt < 2; mt++)
#pragma unroll
                for (int nt = 0; nt < 4; nt++)
                    mma16(acc2[mt][nt], df[mt], bf[nt]);
        }
    }
    __syncthreads();

    float* sO = (float*)sh0;
#pragma unroll
    for (int mt = 0; mt < 2; mt++) {
        int ob = m0 + mh * 32 + mt * 16 + lr;
        float bc0 = cb[ob], bc1 = cb[ob + 8];
        float bd0 = db[ob], bd1 = db[ob + 8];
#pragma unroll
        for (int nt = 0; nt < 4; nt++) {
#pragma unroll
            for (int r = 0; r < 4; r++) {
                float bc = (r >= 2) ? bc1 : bc0;
                float bd = (r >= 2) ? bd1 : bd0;
                int oo = mh * 32 + mt * 16 + lr + ((r >= 2) ? 8 : 0);
                int po = nq * 32 + nt * 8 + lc * 2 + (r & 1);
                float y = fmaxf(fmaxf(acc1[mt][nt][r] + bc, 0.f) + acc2[mt][nt][r] + bd, 0.f);
                sO[po * 68 + oo] = y;
            }
        }
    }
    __syncthreads();
#pragma unroll
    for (int gi = 0; gi < 4; gi++) {
        for (int idx = tid; idx < 480; idx += 256) {
            int t = idx >> 4, q = idx & 15;
            float4 v = *(float4*)&sO[(gi * 32 + t) * 68 + q * 4];
            __half2 h0 = __floats2half2_rn(v.x, v.y);
            __half2 h1 = __floats2half2_rn(v.z, v.w);
            uint2 u;
            u.x = *(uint32_t*)&h0; u.y = *(uint32_t*)&h1;
            *(uint2*)(g_X1h + (size_t)((g0 + gi) * 30 + t) * 128 + m0 + q * 4) = u;
        }
    }
}

// ---------------- fp16 mma TCN block: 3-stage cp.async ring + ldmatrix ----------------
// OUTM: 1 = fp16 [pos][C]; 2 = fp16 transposed [g][c*30+t]
template <int CIN, int COUT, int DIL, int NCH, int OUTM>
__global__ __launch_bounds__(256, 2) void k_tcnH(
    const __half* __restrict__ Xin, const __half* __restrict__ wC,
    const __half* __restrict__ wD, const float* __restrict__ cb,
    const float* __restrict__ db, __half* __restrict__ Xout) {
    constexpr int W = 32 + 2 * DIL;
    constexpr int BB = 4 * W * 40;            // halves per stage: B
    constexpr int AB = 64 * 104;
    constexpr int DB = 64 * 40;
    constexpr int STG = BB + AB + DB;         // halves per stage
    extern __shared__ __half smh[];
    const uint32_t smem0 = (uint32_t)__cvta_generic_to_shared(smh);

    const int tid = threadIdx.x;
    const int wrp = tid >> 5, lane = tid & 31;
    const int lr = lane >> 2, lc = lane & 3;
    const int l8 = lane & 7, s1 = (lane >> 3) & 1, s2 = lane >> 4;
    const int mh = wrp & 1;
    const int nq = wrp >> 1;
    const int mb = blockIdx.x;
    const int m0 = mb * 64;
    const int g0 = blockIdx.y * 4;

    // zero halo rows of all 3 stages
    {
        constexpr int ZR = 2 * DIL + 2;
        uint4 z = make_uint4(0, 0, 0, 0);
        for (int idx = tid; idx < 3 * 4 * ZR * 5; idx += 256) {
            int bufg = idx / (ZR * 5);
            int r = idx - bufg * (ZR * 5);
            int zr = r / 5, pc = r - (r / 5) * 5;
            int u = (zr < 2 * DIL) ? zr : (30 + zr);
            int buf = bufg >> 2, gi = bufg & 3;
            *(uint4*)(smh + buf * STG + (gi * W + u) * 40 + pc * 8) = z;
        }
    }

    auto stage = [&](int chk, int buf) {
        uint32_t sb = smem0 + buf * (STG * 2);
        for (int idx = tid; idx < 480; idx += 256) {
            int gi = idx / 120;
            int r = idx - gi * 120;
            int t = r >> 2, pc = r & 3;
            uint32_t dst = sb + (gi * W + t + 2 * DIL) * 80 + pc * 16;
            const __half* src = Xin + ((size_t)(g0 + gi) * 30 + t) * CIN + chk * 32 + pc * 8;
            CP16(dst, src);
        }
        uint32_t aD = sb + BB * 2;
        const __half* srcA = wC + ((size_t)(mb * NCH + chk) * 64) * 96;
        for (int idx = tid; idx < 768; idx += 256) {
            int o = idx / 12, pc = idx - (idx / 12) * 12;
            CP16(aD + o * 208 + pc * 16, srcA + o * 96 + pc * 8);
        }
        uint32_t dD = sb + (BB + AB) * 2;
        const __half* srcD = wD + ((size_t)(mb * NCH + chk) * 64) * 32;
        {
            int o = tid >> 2, pc = tid & 3;
            CP16(dD + o * 80 + pc * 16, srcD + o * 32 + pc * 8);
        }
        CP_COMMIT();
    };

    float acc1[2][4][4], acc2[2][4][4];
#pragma unroll
    for (int mt = 0; mt < 2; mt++)
#pragma unroll
        for (int nt = 0; nt < 4; nt++)
#pragma unroll
            for (int r = 0; r < 4; r++) { acc1[mt][nt][r] = 0.f; acc2[mt][nt][r] = 0.f; }

    stage(0, 0);
    stage(1, 1);

    for (int chk = 0; chk < NCH; chk++) {
        const int buf = chk % 3;
        if (chk + 1 < NCH) { CP_WAIT1(); } else { CP_WAIT0(); }
        __syncthreads();
        if (chk + 2 < NCH) stage(chk + 2, (chk + 2) % 3);

        const uint32_t sb = smem0 + buf * (STG * 2);
        const uint32_t bRow = sb + nq * (W * 80);
        const uint32_t aB = sb + BB * 2;
        const uint32_t dB = sb + (BB + AB) * 2;

#pragma unroll
        for (int kh = 0; kh < 2; kh++) {
            const uint32_t kb = kh * 32;
#pragma unroll
            for (int tap = 0; tap < 3; tap++) {
                uint32_t bf[4][2];
#pragma unroll
                for (int pr = 0; pr < 2; pr++) {
                    uint32_t ba = bRow +
                        (tap * DIL + (pr * 2 + s2) * 8 + l8) * 80 + kb + s1 * 16;
                    LDMX4(bf[pr * 2][0], bf[pr * 2][1], bf[pr * 2 + 1][0], bf[pr * 2 + 1][1], ba);
                }
                uint32_t af[2][4];
#pragma unroll
                for (int mt = 0; mt < 2; mt++) {
                    uint32_t aa = aB + (mh * 32 + mt * 16 + s1 * 8 + l8) * 208 +
                                  tap * 64 + kb + s2 * 16;
                    LDMX4(af[mt][0], af[mt][1], af[mt][2], af[mt][3], aa);
                }
#pragma unroll
                for (int mt = 0; mt < 2; mt++)
#pragma unroll
                    for (int nt = 0; nt < 4; nt++)
                        mma16(acc1[mt][nt], af[mt], bf[nt]);
                if (tap == 2) {
                    uint32_t df[2][4];
#pragma unroll
                    for (int mt = 0; mt < 2; mt++) {
                        uint32_t da = dB + (mh * 32 + mt * 16 + s1 * 8 + l8) * 80 +
                                      kb + s2 * 16;
                        LDMX4(df[mt][0], df[mt][1], df[mt][2], df[mt][3], da);
                    }
#pragma unroll
                    for (int mt = 0; mt < 2; mt++)
#pragma unroll
                        for (int nt = 0; nt < 4; nt++)
                            mma16(acc2[mt][nt], df[mt], bf[nt]);
                }
            }
        }
        // no trailing sync: next iteration's top sync protects the ring
    }
    __syncthreads();   // all warps done before epilogue overwrites staging smem

    float* sO = (float*)smh;
#pragma unroll
    for (int mt = 0; mt < 2; mt++) {
        int ob = m0 + mh * 32 + mt * 16 + lr;
        float bc0 = cb[ob], bc1 = cb[ob + 8];
        float bd0 = db[ob], bd1 = db[ob + 8];
#pragma unroll
        for (int nt = 0; nt < 4; nt++) {
#pragma unroll
            for (int r = 0; r < 4; r++) {
                float bc = (r >= 2) ? bc1 : bc0;
                float bd = (r >= 2) ? bd1 : bd0;
                int oo = mh * 32 + mt * 16 + lr + ((r >= 2) ? 8 : 0);
                int po = nq * 32 + nt * 8 + lc * 2 + (r & 1);
                float y = fmaxf(fmaxf(acc1[mt][nt][r] + bc, 0.f) + acc2[mt][nt][r] + bd, 0.f);
                sO[po * 68 + oo] = y;
            }
        }
    }
    __syncthreads();
    if (OUTM == 1) {
#pragma unroll
        for (int gi = 0; gi < 4; gi++) {
            for (int idx = tid; idx < 480; idx += 256) {
                int t = idx >> 4, q = idx & 15;
                float4 v = *(float4*)&sO[(gi * 32 + t) * 68 + q * 4];
                __half2 h0 = __floats2half2_rn(v.x, v.y);
                __half2 h1 = __floats2half2_rn(v.z, v.w);
                uint2 u;
                u.x = *(uint32_t*)&h0; u.y = *(uint32_t*)&h1;
                *(uint2*)(Xout + (size_t)((g0 + gi) * 30 + t) * COUT + m0 + q * 4) = u;
            }
        }
    } else {
#pragma unroll
        for (int gi = 0; gi < 4; gi++) {
            for (int idx = tid; idx < 960; idx += 256) {
                int c = idx / 15, th = idx - (idx / 15) * 15;
                int t = th * 2;
                float a = sO[(gi * 32 + t) * 68 + c];
                float b = sO[(gi * 32 + t + 1) * 68 + c];
                __half2 h = __floats2half2_rn(a, b);
                *(__half2*)(Xout + (size_t)(g0 + gi) * 3840 + (m0 + c) * 30 + t) = h;
            }
        }
    }
}

// ---------------- tensor-core FC: GF=32 graphs per CTA ----------------
#define FC_XST 40
#define FC_XBUF (32 * 40)                       // halves per kss X slab
#define FC_WBUF (80 * 40)
#define FC_STRIDE (8 * FC_XBUF + 8 * FC_WBUF)   // halves per buffer
#define FC_SMEM (2 * FC_STRIDE * 2)             // bytes

__global__ __launch_bounds__(256, 1) void k_fcM(
    const __half* __restrict__ X3T, const __half* __restrict__ fcwH,
    const float* __restrict__ fcb, float* __restrict__ out) {
    extern __shared__ __half sh[];
    const uint32_t s0 = (uint32_t)__cvta_generic_to_shared(sh);
    const int tid = threadIdx.x;
    const int wrp = tid >> 5, lane = tid & 31;
    const int l8 = lane & 7, s1 = (lane >> 3) & 1, s2 = lane >> 4;
    const int lr = lane >> 2, lc = lane & 3;
    const int g0 = blockIdx.x * 32;
    const int ks = wrp;

    auto stage = [&](int ch, int buf) {
        uint32_t base = s0 + buf * (FC_STRIDE * 2);
        for (int i = tid; i < 1024; i += 256) {
            int kss = i >> 7, r = i & 127;
            int g = r >> 2, q = r & 3;
            uint32_t dst = base + (kss * FC_XBUF + g * FC_XST) * 2 + q * 16;
            const __half* src = X3T + (size_t)(g0 + g) * 3840 + kss * 480 + ch * 32 + q * 8;
            CP16(dst, src);
        }
        for (int i = tid; i < 2560; i += 256) {
            int kss = i / 320, r = i - kss * 320;
            int j = r >> 2, q = r & 3;
            uint32_t dst = base + (8 * FC_XBUF + kss * FC_WBUF + j * FC_XST) * 2 + q * 16;
            const __half* src = fcwH + (size_t)(j < FCO ? j : 0) * 3840 + kss * 480 + ch * 32 + q * 8;
            if (j < FCO) CP16(dst, src); else CP16Z(dst, src);
        }
        CP_COMMIT();
    };

    float acc[2][10][4];
#pragma unroll
    for (int mt = 0; mt < 2; mt++)
#pragma unroll
        for (int nt = 0; nt < 10; nt++)
#pragma unroll
            for (int r = 0; r < 4; r++) acc[mt][nt][r] = 0.f;

    stage(0, 0);
    stage(1, 1);

    for (int ch = 0; ch < 15; ch++) {
        int buf = ch & 1;
        if (ch + 1 < 15) { CP_WAIT1(); } else { CP_WAIT0(); }
        __syncthreads();
        uint32_t xB = s0 + buf * (FC_STRIDE * 2) + ks * (FC_XBUF * 2);
        uint32_t wB = s0 + buf * (FC_STRIDE * 2) + (8 * FC_XBUF + ks * FC_WBUF) * 2;
#pragma unroll
        for (int k16 = 0; k16 < 2; k16++) {
            uint32_t kb = k16 * 32;
            uint32_t af[2][4];
#pragma unroll
            for (int mt = 0; mt < 2; mt++)
                LDMX4(af[mt][0], af[mt][1], af[mt][2], af[mt][3],
                      xB + (mt * 16 + s1 * 8 + l8) * 80 + kb + s2 * 16);
            uint32_t bf[10][2];
#pragma unroll
            for (int jt = 0; jt < 5; jt++) {
                LDMX4(bf[jt * 2][0], bf[jt * 2][1], bf[jt * 2 + 1][0], bf[jt * 2 + 1][1],
                      wB + (jt * 16 + s2 * 8 + l8) * 80 + kb + s1 * 16);
            }
#pragma unroll
            for (int mt = 0; mt < 2; mt++)
#pragma unroll
                for (int nt = 0; nt < 10; nt++) mma16(acc[mt][nt], af[mt], bf[nt]);
        }
        __syncthreads();
        if (ch + 2 < 15) stage(ch + 2, buf);
    }

    __syncthreads();
    float* sred = (float*)sh;   // [8][32][80]
#pragma unroll
    for (int mt = 0; mt < 2; mt++)
#pragma unroll
        for (int nt = 0; nt < 10; nt++)
#pragma unroll
            for (int r = 0; r < 4; r++) {
                int g = mt * 16 + lr + ((r & 2) ? 8 : 0);
                int j = nt * 8 + lc * 2 + (r & 1);
                sred[(ks * 32 + g) * 80 + j] = acc[mt][nt][r];
            }
    __syncthreads();
    for (int idx = tid; idx < 32 * FCO; idx += 256) {
        int g = idx / FCO, j = idx - (idx / FCO) * FCO;
        float s = 0.f;
#pragma unroll
        for (int w2 = 0; w2 < 8; w2++) s += sred[(w2 * 32 + g) * 80 + j];
        out[(size_t)(g0 + g) * FCO + j] = s + fcb[j];
    }
}

// ---------------- launch ----------------
extern "C" void kernel_launch(void* const* d_in, const int* in_sizes, int n_in,
                              void* d_out, int out_size) {
    const float* x    = (const float*)d_in[0];
    const void*  ei   = d_in[1];
    const float* gcnw = (const float*)d_in[2];
    const float* gcnb = (const float*)d_in[3];
    const float* cw0  = (const float*)d_in[4];
    const float* cb0  = (const float*)d_in[5];
    const float* dw0  = (const float*)d_in[6];
    const float* db0  = (const float*)d_in[7];
    const float* cw1  = (const float*)d_in[8];
    const float* cb1  = (const float*)d_in[9];
    const float* dw1  = (const float*)d_in[10];
    const float* db1  = (const float*)d_in[11];
    const float* cw2  = (const float*)d_in[12];
    const float* cb2  = (const float*)d_in[13];
    const float* dw2  = (const float*)d_in[14];
    const float* db2  = (const float*)d_in[15];
    const float* fcw  = (const float*)d_in[16];
    const float* fcb  = (const float*)d_in[17];
    float* out = (float*)d_out;

    void *pX1h, *pX2h, *pX3T, *pDeg, *pAcc;
    void *pWC0, *pWD0, *pWC1, *pWD1, *pWC2, *pWD2, *pFcwH;
    cudaGetSymbolAddress(&pX1h, g_X1h);
    cudaGetSymbolAddress(&pX2h, g_X2h);
    cudaGetSymbolAddress(&pX3T, g_X3T);
    cudaGetSymbolAddress(&pDeg, g_deg);
    cudaGetSymbolAddress(&pAcc, g_acc);
    cudaGetSymbolAddress(&pWC0, g_wC0);
    cudaGetSymbolAddress(&pWD0, g_wD0);
    cudaGetSymbolAddress(&pWC1, g_wC1);
    cudaGetSymbolAddress(&pWD1, g_wD1);
    cudaGetSymbolAddress(&pWC2, g_wC2);
    cudaGetSymbolAddress(&pWD2, g_wD2);
    cudaGetSymbolAddress(&pFcwH, g_fcwH);

    cudaMemsetAsync(pDeg, 0, NTOT * sizeof(float));
    cudaMemsetAsync(pAcc, 0, NTOT * 12 * sizeof(float));

    k_linDeg<<<5320, 256>>>(x, gcnw, ei, cw0, dw0, cw1, dw1, cw2, dw2, fcw);
    k_scatter<<<NE / 256, 256>>>(ei);

    cudaFuncSetAttribute(k_tcn0M, cudaFuncAttributeMaxDynamicSharedMemorySize, SM0_BYTES);
    k_tcn0M<<<dim3(2, NB / 4), 256, SM0_BYTES>>>(
        (const __half*)pWC0, (const __half*)pWD0, cb0, db0, gcnb);

    constexpr int SM1 = 3 * (4 * 38 * 40 + 64 * 104 + 64 * 40) * 2;
    constexpr int SM2 = 3 * (4 * 50 * 40 + 64 * 104 + 64 * 40) * 2;
    cudaFuncSetAttribute((const void*)k_tcnH<128, 512, 3, 4, 1>,
                         cudaFuncAttributeMaxDynamicSharedMemorySize, SM1);
    cudaFuncSetAttribute((const void*)k_tcnH<512, 128, 9, 16, 2>,
                         cudaFuncAttributeMaxDynamicSharedMemorySize, SM2);
    k_tcnH<128, 512, 3, 4, 1><<<dim3(8, NB / 4), 256, SM1>>>(
        (const __half*)pX1h, (const __half*)pWC1, (const __half*)pWD1, cb1, db1,
        (__half*)pX2h);
    k_tcnH<512, 128, 9, 16, 2><<<dim3(2, NB / 4), 256, SM2>>>(
        (const __half*)pX2h, (const __half*)pWC2, (const __half*)pWD2, cb2, db2,
        (__half*)pX3T);

    cudaFuncSetAttribute(k_fcM, cudaFuncAttributeMaxDynamicSharedMemorySize, FC_SMEM);
    k_fcM<<<NB / 32, 256, FC_SMEM>>>((const __half*)pX3T, (const __half*)pFcwH, fcb, out);
}